// round 1
// baseline (speedup 1.0000x reference)
#include <cuda_runtime.h>

// LinearEdgeDecoder: out[e] = relu(concat(x[row[e]], x[col[e]]) @ W1 + b1) @ W2 + b2
// E = 1.5M edges, D = 128, H1 = 256, H2 = 128.
//
// Strategy: fused register-blocked SGEMM.
//   - CTA tile: 128 edges (M) x 128 hidden (N), K = 256 walked in 16-wide slices.
//   - A-tile is a gather: K slices 0..7 come from x[row[e]], 8..15 from x[col[e]].
//     x (51.2 MB) fits in L2, so gathers are L2 hits.
//   - 256 threads, each computes an 8x8 micro-tile (64 FMA per 32B of LDS) -> FMA bound.
//   - Double-buffered smem with register prefetch (LDG next slice while computing).
//   - Epilogue fuses +b1, relu, dot with W2, +b2; 16-lane butterfly reduction; one
//     coalesced f32 store per edge. Second matmul never materialized.
//
// Index dtype: reference asks for int64 but JAX downcasts to int32 unless x64 is
// enabled. A tiny detection kernel checks whether the int64 interpretation yields
// valid node ids (< N_NODES); int32 data read as int64 fuses two indices into a
// huge value, so 64 probes give certain detection. Result lives in a __device__
// global read by the main kernel (same stream -> ordered; deterministic).

#define TILE_M 128
#define TILE_N 128
#define KT     16
#define NTHREADS 256

__device__ int g_idx_is64;

__global__ void detect_idx_dtype(const void* __restrict__ eidx, int n_nodes) {
    if (blockIdx.x == 0 && threadIdx.x == 0) {
        const long long* p = (const long long*)eidx;
        int ok = 1;
        #pragma unroll 1
        for (int i = 0; i < 64; ++i) {
            long long v = p[i];
            if (v < 0 || v >= (long long)n_nodes) { ok = 0; break; }
        }
        g_idx_is64 = ok;
    }
}

__global__ __launch_bounds__(NTHREADS) void edge_decoder_kernel(
    const float* __restrict__ x,          // [N_NODES, 128]
    const void*  __restrict__ eidx,       // [2, E] int32 or int64
    const float* __restrict__ W1,         // [256, 128]
    const float* __restrict__ b1,         // [128]
    const float* __restrict__ W2,         // [128]
    const float* __restrict__ b2,         // [1]
    float* __restrict__ out,              // [E]
    int E)
{
    __shared__ float As[2][KT * TILE_M];      // [k][m], transposed for vector LDS along m
    __shared__ float Bs[2][KT * TILE_N];      // [k][n]
    __shared__ int   sRow[TILE_M];
    __shared__ int   sCol[TILE_M];

    const int tid = threadIdx.x;
    const long long base = (long long)blockIdx.x * TILE_M;

    // ---- load edge indices for this tile (dtype-dispatched) ----
    {
        const int is64 = g_idx_is64;
        int m = tid & 127;
        long long e = base + m;
        long long ec = (e < E) ? e : 0;       // clamp tail: garbage-but-valid gather, store guarded
        if (tid < 128) {
            sRow[m] = is64 ? (int)((const long long*)eidx)[ec]
                           : ((const int*)eidx)[ec];
        } else {
            sCol[m] = is64 ? (int)((const long long*)eidx)[(long long)E + ec]
                           : ((const int*)eidx)[(long long)E + ec];
        }
    }
    __syncthreads();

    const float4* __restrict__ x4 = (const float4*)x;
    const float4* __restrict__ w4 = (const float4*)W1;

    // loader assignments (each thread: 2 float4 of A, 2 float4 of B per K-slice)
    const int mA  = tid & 127;     // edge within tile
    const int gA  = tid >> 7;      // float4 group 0/1 (also loads gA+2)
    const int kB  = tid >> 5;      // 0..7 (also kB+8)
    const int nqB = tid & 31;      // float4 column

    float4 ra0, ra1, rb0, rb1;

    // compute assignments: 8x8 micro-tile
    const int tx = tid & 15;       // -> n block
    const int ty = tid >> 4;       // -> m block

    float acc[8][8];
    #pragma unroll
    for (int i = 0; i < 8; ++i)
        #pragma unroll
        for (int j = 0; j < 8; ++j) acc[i][j] = 0.f;

    // ---- prefetch slice 0 ----
    {
        int node = sRow[mA];
        int kq = 0;
        ra0 = x4[(long long)node * 32 + kq + gA];
        ra1 = x4[(long long)node * 32 + kq + gA + 2];
        rb0 = w4[(0 + kB) * 32 + nqB];
        rb1 = w4[(0 + kB + 8) * 32 + nqB];
    }
    // store slice 0 into buffer 0
    {
        float* A = As[0]; float* B = Bs[0];
        int k0 = 4 * gA;
        A[(k0 + 0) * TILE_M + mA] = ra0.x;
        A[(k0 + 1) * TILE_M + mA] = ra0.y;
        A[(k0 + 2) * TILE_M + mA] = ra0.z;
        A[(k0 + 3) * TILE_M + mA] = ra0.w;
        int k2 = 4 * (gA + 2);
        A[(k2 + 0) * TILE_M + mA] = ra1.x;
        A[(k2 + 1) * TILE_M + mA] = ra1.y;
        A[(k2 + 2) * TILE_M + mA] = ra1.z;
        A[(k2 + 3) * TILE_M + mA] = ra1.w;
        ((float4*)B)[kB * 32 + nqB]       = rb0;
        ((float4*)B)[(kB + 8) * 32 + nqB] = rb1;
    }
    __syncthreads();

    // ---- main loop over 16 K-slices (0..7: row half, 8..15: col half) ----
    #pragma unroll 1
    for (int kt = 0; kt < 16; ++kt) {
        if (kt < 15) {
            int ktn = kt + 1;
            int node = (ktn < 8) ? sRow[mA] : sCol[mA];
            int kq = (ktn & 7) * 4;
            ra0 = x4[(long long)node * 32 + kq + gA];
            ra1 = x4[(long long)node * 32 + kq + gA + 2];
            int kg = ktn * KT;
            rb0 = w4[(kg + kB) * 32 + nqB];
            rb1 = w4[(kg + kB + 8) * 32 + nqB];
        }

        const float* A = As[kt & 1];
        const float* B = Bs[kt & 1];
        #pragma unroll
        for (int k = 0; k < KT; ++k) {
            float4 a0 = ((const float4*)(A + k * TILE_M))[ty * 2];
            float4 a1 = ((const float4*)(A + k * TILE_M))[ty * 2 + 1];
            float4 c0 = ((const float4*)(B + k * TILE_N))[tx * 2];
            float4 c1 = ((const float4*)(B + k * TILE_N))[tx * 2 + 1];
            float av[8] = {a0.x, a0.y, a0.z, a0.w, a1.x, a1.y, a1.z, a1.w};
            float bv[8] = {c0.x, c0.y, c0.z, c0.w, c1.x, c1.y, c1.z, c1.w};
            #pragma unroll
            for (int i = 0; i < 8; ++i)
                #pragma unroll
                for (int j = 0; j < 8; ++j)
                    acc[i][j] = fmaf(av[i], bv[j], acc[i][j]);
        }

        if (kt < 15) {
            float* A2 = As[(kt + 1) & 1]; float* B2 = Bs[(kt + 1) & 1];
            int k0 = 4 * gA;
            A2[(k0 + 0) * TILE_M + mA] = ra0.x;
            A2[(k0 + 1) * TILE_M + mA] = ra0.y;
            A2[(k0 + 2) * TILE_M + mA] = ra0.z;
            A2[(k0 + 3) * TILE_M + mA] = ra0.w;
            int k2 = 4 * (gA + 2);
            A2[(k2 + 0) * TILE_M + mA] = ra1.x;
            A2[(k2 + 1) * TILE_M + mA] = ra1.y;
            A2[(k2 + 2) * TILE_M + mA] = ra1.z;
            A2[(k2 + 3) * TILE_M + mA] = ra1.w;
            ((float4*)B2)[kB * 32 + nqB]       = rb0;
            ((float4*)B2)[(kB + 8) * 32 + nqB] = rb1;
            __syncthreads();
        }
    }

    // ---- fused epilogue: h = relu(acc + b1); s = h . W2; out = s + b2 ----
    const int myN = tx * 8;
    const int myM = ty * 8;
    float b1v[8], w2v[8];
    #pragma unroll
    for (int j = 0; j < 8; ++j) {
        b1v[j] = b1[myN + j];
        w2v[j] = W2[myN + j];
    }
    const float bias2 = b2[0];

    #pragma unroll
    for (int i = 0; i < 8; ++i) {
        float s = 0.f;
        #pragma unroll
        for (int j = 0; j < 8; ++j) {
            float h = acc[i][j] + b1v[j];
            h = fmaxf(h, 0.f);
            s = fmaf(h, w2v[j], s);
        }
        // reduce across the 16 tx lanes (stays within 16-lane groups)
        s += __shfl_xor_sync(0xffffffffu, s, 8);
        s += __shfl_xor_sync(0xffffffffu, s, 4);
        s += __shfl_xor_sync(0xffffffffu, s, 2);
        s += __shfl_xor_sync(0xffffffffu, s, 1);
        if (tx == 0) {
            long long e = base + myM + i;
            if (e < E) out[e] = s + bias2;
        }
    }
}

extern "C" void kernel_launch(void* const* d_in, const int* in_sizes, int n_in,
                              void* d_out, int out_size)
{
    const float* x   = (const float*)d_in[0];
    const void*  ei  = d_in[1];
    const float* W1  = (const float*)d_in[2];
    const float* b1  = (const float*)d_in[3];
    const float* W2  = (const float*)d_in[4];
    const float* b2  = (const float*)d_in[5];
    float* out = (float*)d_out;

    int n_nodes = in_sizes[0] / 128;
    int E = in_sizes[1] / 2;

    detect_idx_dtype<<<1, 32>>>(ei, n_nodes);

    int grid = (E + TILE_M - 1) / TILE_M;
    edge_decoder_kernel<<<grid, NTHREADS>>>(x, ei, W1, b1, W2, b2, out, E);
}

// round 2
// speedup vs baseline: 7.0345x; 7.0345x over previous
#include <cuda_runtime.h>

// LinearEdgeDecoder, factored:
//   uv[n][0:128]   = x[n] @ W1[0:128,:]   + b1     (u, bias folded)
//   uv[n][128:256] = x[n] @ W1[128:256,:]          (v)
//   out[e] = relu(uv[row[e]][0:128] + uv[col[e]][128:256]) . W2 + b2
//
// FLOPs drop 98.7 GF -> 6.6 GF (node GEMM) + 0.6 GF (edge phase); the edge phase
// is a 1.5 GB L2-resident gather (uv table = 102 MB < 126 MB L2).
//
// Index dtype sniffing as in R1 (JAX silently downcasts int64->int32 w/o x64).

#define PT_M 128
#define PT_N 128
#define PKT  16
#define NT   256

__device__ int g_idx_is64;
__device__ float g_uv[131072 * 256];   // node scratch, static (no allocs allowed)

__global__ void detect_idx_dtype(const void* __restrict__ eidx, int n_nodes) {
    if (blockIdx.x == 0 && threadIdx.x == 0) {
        const long long* p = (const long long*)eidx;
        int ok = 1;
        #pragma unroll 1
        for (int i = 0; i < 64; ++i) {
            long long v = p[i];
            if (v < 0 || v >= (long long)n_nodes) { ok = 0; break; }
        }
        g_idx_is64 = ok;
    }
}

// ---------------- node-table GEMM: uv = x @ W1(+b1) ----------------
// grid = (ceil(n_nodes/128), 2): y selects which 128-row half of W1 (u vs v).
__global__ __launch_bounds__(NT) void precompute_uv(
    const float* __restrict__ x,    // [n_nodes, 128]
    const float* __restrict__ W1,   // [256, 128]
    const float* __restrict__ b1,   // [128]
    int n_nodes)
{
    __shared__ float As[2][PKT * PT_M];
    __shared__ float Bs[2][PKT * PT_N];

    const int tid  = threadIdx.x;
    const int base = blockIdx.x * PT_M;
    const int half = blockIdx.y;        // 0 -> u (W1 rows 0..127, +b1), 1 -> v

    const float4* __restrict__ x4 = (const float4*)x;
    const float4* __restrict__ w4 = (const float4*)W1;

    const int mA  = tid & 127;
    const int gA  = tid >> 7;
    const int kB  = tid >> 5;
    const int nqB = tid & 31;
    int nodeA = base + mA;
    if (nodeA >= n_nodes) nodeA = 0;    // clamp; stores guarded

    const int tx = tid & 15;
    const int ty = tid >> 4;

    float acc[8][8];
    #pragma unroll
    for (int i = 0; i < 8; ++i)
        #pragma unroll
        for (int j = 0; j < 8; ++j) acc[i][j] = 0.f;

    float4 ra0, ra1, rb0, rb1;

    // prefetch slice 0 into buffer 0
    ra0 = x4[(long long)nodeA * 32 + gA];
    ra1 = x4[(long long)nodeA * 32 + gA + 2];
    rb0 = w4[(half * 128 + kB) * 32 + nqB];
    rb1 = w4[(half * 128 + kB + 8) * 32 + nqB];
    {
        float* A = As[0]; float* B = Bs[0];
        int k0 = 4 * gA;
        A[(k0 + 0) * PT_M + mA] = ra0.x;
        A[(k0 + 1) * PT_M + mA] = ra0.y;
        A[(k0 + 2) * PT_M + mA] = ra0.z;
        A[(k0 + 3) * PT_M + mA] = ra0.w;
        int k2 = 4 * (gA + 2);
        A[(k2 + 0) * PT_M + mA] = ra1.x;
        A[(k2 + 1) * PT_M + mA] = ra1.y;
        A[(k2 + 2) * PT_M + mA] = ra1.z;
        A[(k2 + 3) * PT_M + mA] = ra1.w;
        ((float4*)B)[kB * 32 + nqB]       = rb0;
        ((float4*)B)[(kB + 8) * 32 + nqB] = rb1;
    }
    __syncthreads();

    #pragma unroll 1
    for (int kt = 0; kt < 8; ++kt) {          // K = 128 -> 8 slices of 16
        if (kt < 7) {
            int ktn = kt + 1;
            ra0 = x4[(long long)nodeA * 32 + ktn * 4 + gA];
            ra1 = x4[(long long)nodeA * 32 + ktn * 4 + gA + 2];
            int kg = half * 128 + ktn * PKT;
            rb0 = w4[(kg + kB) * 32 + nqB];
            rb1 = w4[(kg + kB + 8) * 32 + nqB];
        }

        const float* A = As[kt & 1];
        const float* B = Bs[kt & 1];
        #pragma unroll
        for (int k = 0; k < PKT; ++k) {
            float4 a0 = ((const float4*)(A + k * PT_M))[ty * 2];
            float4 a1 = ((const float4*)(A + k * PT_M))[ty * 2 + 1];
            float4 c0 = ((const float4*)(B + k * PT_N))[tx * 2];
            float4 c1 = ((const float4*)(B + k * PT_N))[tx * 2 + 1];
            float av[8] = {a0.x, a0.y, a0.z, a0.w, a1.x, a1.y, a1.z, a1.w};
            float bv[8] = {c0.x, c0.y, c0.z, c0.w, c1.x, c1.y, c1.z, c1.w};
            #pragma unroll
            for (int i = 0; i < 8; ++i)
                #pragma unroll
                for (int j = 0; j < 8; ++j)
                    acc[i][j] = fmaf(av[i], bv[j], acc[i][j]);
        }

        if (kt < 7) {
            float* A2 = As[(kt + 1) & 1]; float* B2 = Bs[(kt + 1) & 1];
            int k0 = 4 * gA;
            A2[(k0 + 0) * PT_M + mA] = ra0.x;
            A2[(k0 + 1) * PT_M + mA] = ra0.y;
            A2[(k0 + 2) * PT_M + mA] = ra0.z;
            A2[(k0 + 3) * PT_M + mA] = ra0.w;
            int k2 = 4 * (gA + 2);
            A2[(k2 + 0) * PT_M + mA] = ra1.x;
            A2[(k2 + 1) * PT_M + mA] = ra1.y;
            A2[(k2 + 2) * PT_M + mA] = ra1.z;
            A2[(k2 + 3) * PT_M + mA] = ra1.w;
            ((float4*)B2)[kB * 32 + nqB]       = rb0;
            ((float4*)B2)[(kB + 8) * 32 + nqB] = rb1;
            __syncthreads();
        }
    }

    // epilogue: fold b1 into the u half, store fp32 rows of uv
    float b1v[8];
    #pragma unroll
    for (int j = 0; j < 8; ++j) b1v[j] = (half == 0) ? b1[tx * 8 + j] : 0.f;

    #pragma unroll
    for (int i = 0; i < 8; ++i) {
        int node = base + ty * 8 + i;
        if (node < n_nodes) {
            float4 s0 = make_float4(acc[i][0] + b1v[0], acc[i][1] + b1v[1],
                                    acc[i][2] + b1v[2], acc[i][3] + b1v[3]);
            float4 s1 = make_float4(acc[i][4] + b1v[4], acc[i][5] + b1v[5],
                                    acc[i][6] + b1v[6], acc[i][7] + b1v[7]);
            float* dst = g_uv + (size_t)node * 256 + half * 128 + tx * 8;
            ((float4*)dst)[0] = s0;
            ((float4*)dst)[1] = s1;
        }
    }
}

// ---------------- edge phase: gather-add-relu-dot ----------------
// 1 warp handles 4 edges (batched loads -> MLP=8 float4/lane in flight).
__global__ __launch_bounds__(256) void edge_eval(
    const void*  __restrict__ eidx,
    const float* __restrict__ W2,   // [128]
    const float* __restrict__ b2,   // [1]
    float* __restrict__ out,
    int E)
{
    const int lane = threadIdx.x & 31;
    const int warp = blockIdx.x * (blockDim.x >> 5) + (threadIdx.x >> 5);
    const long long e0 = (long long)warp * 4;
    if (e0 >= E) return;

    const float4 w2v = ((const float4*)W2)[lane];
    const float  bias = b2[0];
    const int    is64 = g_idx_is64;
    const float4* __restrict__ uv4 = (const float4*)g_uv;

    int rows[4], cols[4];
    #pragma unroll
    for (int t = 0; t < 4; ++t) {
        long long e = e0 + t;
        long long ec = (e < E) ? e : e0;
        if (is64) {
            rows[t] = (int)((const long long*)eidx)[ec];
            cols[t] = (int)((const long long*)eidx)[(long long)E + ec];
        } else {
            rows[t] = ((const int*)eidx)[ec];
            cols[t] = ((const int*)eidx)[(long long)E + ec];
        }
    }

    float4 u[4], v[4];
    #pragma unroll
    for (int t = 0; t < 4; ++t) {
        u[t] = uv4[(long long)rows[t] * 64 + lane];        // u half
        v[t] = uv4[(long long)cols[t] * 64 + 32 + lane];   // v half
    }

    #pragma unroll
    for (int t = 0; t < 4; ++t) {
        float s;
        s = fmaxf(u[t].x + v[t].x, 0.f) * w2v.x;
        s = fmaf(fmaxf(u[t].y + v[t].y, 0.f), w2v.y, s);
        s = fmaf(fmaxf(u[t].z + v[t].z, 0.f), w2v.z, s);
        s = fmaf(fmaxf(u[t].w + v[t].w, 0.f), w2v.w, s);
        s += __shfl_xor_sync(0xffffffffu, s, 16);
        s += __shfl_xor_sync(0xffffffffu, s, 8);
        s += __shfl_xor_sync(0xffffffffu, s, 4);
        s += __shfl_xor_sync(0xffffffffu, s, 2);
        s += __shfl_xor_sync(0xffffffffu, s, 1);
        if (lane == 0 && e0 + t < E) out[e0 + t] = s + bias;
    }
}

extern "C" void kernel_launch(void* const* d_in, const int* in_sizes, int n_in,
                              void* d_out, int out_size)
{
    const float* x   = (const float*)d_in[0];
    const void*  ei  = d_in[1];
    const float* W1  = (const float*)d_in[2];
    const float* b1  = (const float*)d_in[3];
    const float* W2  = (const float*)d_in[4];
    const float* b2  = (const float*)d_in[5];
    float* out = (float*)d_out;

    int n_nodes = in_sizes[0] / 128;
    int E = in_sizes[1] / 2;

    detect_idx_dtype<<<1, 32>>>(ei, n_nodes);

    dim3 pgrid((n_nodes + PT_M - 1) / PT_M, 2);
    precompute_uv<<<pgrid, NT>>>(x, W1, b1, n_nodes);

    long long warps = ((long long)E + 3) / 4;
    int blocks = (int)((warps + 7) / 8);
    edge_eval<<<blocks, 256>>>(ei, W2, b2, out, E);
}

// round 4
// speedup vs baseline: 8.0871x; 1.1496x over previous
#include <cuda_runtime.h>
#include <cuda_fp16.h>

// LinearEdgeDecoder, factored + fp16-compressed node table:
//   uv[n][0:128]   = fp16( x[n] @ W1[0:128,:] + b1 )   (u)
//   uv[n][128:256] = fp16( x[n] @ W1[128:256,:] )      (v)
//   out[e] = relu(f32(u[row[e]]) + f32(v[col[e]])) . W2 + b2
//
// fp16 halves the edge-phase gather (1.5GB -> 768MB, LTS-bound) and the table
// (102MB -> 64MB, fully L2-resident). fp16 rounding contributes ~3e-4 RMS rel
// error through the W2 dot -- under the 1e-3 gate.

#define PT_M 128
#define PT_N 128
#define PKT  16
#define NT   256

__device__ int    g_idx_is64;
__device__ __half g_uv[(size_t)131072 * 256];   // static scratch (no allocs allowed)

__device__ __forceinline__ unsigned h2_bits(__half2 h) {
    return *reinterpret_cast<unsigned*>(&h);
}
__device__ __forceinline__ float2 bits_f2(unsigned b) {
    return __half22float2(*reinterpret_cast<__half2*>(&b));
}

__global__ void detect_idx_dtype(const void* __restrict__ eidx, int n_nodes) {
    // 32 lanes each probe 2 int64 slots; int32 data read as int64 fuses pairs
    // into huge/negative values -> certain detection over 64 probes.
    const long long* p = (const long long*)eidx;
    int lane = threadIdx.x;
    int bad = 0;
    #pragma unroll
    for (int t = 0; t < 2; ++t) {
        long long v = p[lane * 2 + t];
        if (v < 0 || v >= (long long)n_nodes) bad = 1;
    }
    unsigned m = __ballot_sync(0xffffffffu, bad);
    if (lane == 0) g_idx_is64 = (m == 0u);
}

// ---------------- node-table GEMM: uv = fp16(x @ W1 (+b1)) ----------------
__global__ __launch_bounds__(NT) void precompute_uv(
    const float* __restrict__ x,    // [n_nodes, 128]
    const float* __restrict__ W1,   // [256, 128]
    const float* __restrict__ b1,   // [128]
    int n_nodes)
{
    __shared__ float As[2][PKT * PT_M];
    __shared__ float Bs[2][PKT * PT_N];

    const int tid  = threadIdx.x;
    const int base = blockIdx.x * PT_M;
    const int half = blockIdx.y;        // 0 -> u (+b1), 1 -> v

    const float4* __restrict__ x4 = (const float4*)x;
    const float4* __restrict__ w4 = (const float4*)W1;

    const int mA  = tid & 127;
    const int gA  = tid >> 7;
    const int kB  = tid >> 5;
    const int nqB = tid & 31;
    int nodeA = base + mA;
    if (nodeA >= n_nodes) nodeA = 0;

    const int tx = tid & 15;
    const int ty = tid >> 4;

    float acc[8][8];
    #pragma unroll
    for (int i = 0; i < 8; ++i)
        #pragma unroll
        for (int j = 0; j < 8; ++j) acc[i][j] = 0.f;

    float4 ra0, ra1, rb0, rb1;

    ra0 = x4[(long long)nodeA * 32 + gA];
    ra1 = x4[(long long)nodeA * 32 + gA + 2];
    rb0 = w4[(half * 128 + kB) * 32 + nqB];
    rb1 = w4[(half * 128 + kB + 8) * 32 + nqB];
    {
        float* A = As[0]; float* B = Bs[0];
        int k0 = 4 * gA;
        A[(k0 + 0) * PT_M + mA] = ra0.x;
        A[(k0 + 1) * PT_M + mA] = ra0.y;
        A[(k0 + 2) * PT_M + mA] = ra0.z;
        A[(k0 + 3) * PT_M + mA] = ra0.w;
        int k2 = 4 * (gA + 2);
        A[(k2 + 0) * PT_M + mA] = ra1.x;
        A[(k2 + 1) * PT_M + mA] = ra1.y;
        A[(k2 + 2) * PT_M + mA] = ra1.z;
        A[(k2 + 3) * PT_M + mA] = ra1.w;
        ((float4*)B)[kB * 32 + nqB]       = rb0;
        ((float4*)B)[(kB + 8) * 32 + nqB] = rb1;
    }
    __syncthreads();

    #pragma unroll 1
    for (int kt = 0; kt < 8; ++kt) {
        if (kt < 7) {
            int ktn = kt + 1;
            ra0 = x4[(long long)nodeA * 32 + ktn * 4 + gA];
            ra1 = x4[(long long)nodeA * 32 + ktn * 4 + gA + 2];
            int kg = half * 128 + ktn * PKT;
            rb0 = w4[(kg + kB) * 32 + nqB];
            rb1 = w4[(kg + kB + 8) * 32 + nqB];
        }

        const float* A = As[kt & 1];
        const float* B = Bs[kt & 1];
        #pragma unroll
        for (int k = 0; k < PKT; ++k) {
            float4 a0 = ((const float4*)(A + k * PT_M))[ty * 2];
            float4 a1 = ((const float4*)(A + k * PT_M))[ty * 2 + 1];
            float4 c0 = ((const float4*)(B + k * PT_N))[tx * 2];
            float4 c1 = ((const float4*)(B + k * PT_N))[tx * 2 + 1];
            float av[8] = {a0.x, a0.y, a0.z, a0.w, a1.x, a1.y, a1.z, a1.w};
            float bv[8] = {c0.x, c0.y, c0.z, c0.w, c1.x, c1.y, c1.z, c1.w};
            #pragma unroll
            for (int i = 0; i < 8; ++i)
                #pragma unroll
                for (int j = 0; j < 8; ++j)
                    acc[i][j] = fmaf(av[i], bv[j], acc[i][j]);
        }

        if (kt < 7) {
            float* A2 = As[(kt + 1) & 1]; float* B2 = Bs[(kt + 1) & 1];
            int k0 = 4 * gA;
            A2[(k0 + 0) * PT_M + mA] = ra0.x;
            A2[(k0 + 1) * PT_M + mA] = ra0.y;
            A2[(k0 + 2) * PT_M + mA] = ra0.z;
            A2[(k0 + 3) * PT_M + mA] = ra0.w;
            int k2 = 4 * (gA + 2);
            A2[(k2 + 0) * PT_M + mA] = ra1.x;
            A2[(k2 + 1) * PT_M + mA] = ra1.y;
            A2[(k2 + 2) * PT_M + mA] = ra1.z;
            A2[(k2 + 3) * PT_M + mA] = ra1.w;
            ((float4*)B2)[kB * 32 + nqB]       = rb0;
            ((float4*)B2)[(kB + 8) * 32 + nqB] = rb1;
            __syncthreads();
        }
    }

    // epilogue: (+b1 on u half), convert to fp16, one uint4 store per 8 features
    float b1v[8];
    #pragma unroll
    for (int j = 0; j < 8; ++j) b1v[j] = (half == 0) ? b1[tx * 8 + j] : 0.f;

    #pragma unroll
    for (int i = 0; i < 8; ++i) {
        int node = base + ty * 8 + i;
        if (node < n_nodes) {
            uint4 pk;
            pk.x = h2_bits(__floats2half2_rn(acc[i][0] + b1v[0], acc[i][1] + b1v[1]));
            pk.y = h2_bits(__floats2half2_rn(acc[i][2] + b1v[2], acc[i][3] + b1v[3]));
            pk.z = h2_bits(__floats2half2_rn(acc[i][4] + b1v[4], acc[i][5] + b1v[5]));
            pk.w = h2_bits(__floats2half2_rn(acc[i][6] + b1v[6], acc[i][7] + b1v[7]));
            __half* dst = g_uv + (size_t)node * 256 + half * 128 + tx * 8;
            *((uint4*)dst) = pk;
        }
    }
}

// ---------------- edge phase: fp16 gather-add-relu-dot ----------------
__global__ __launch_bounds__(256) void edge_eval(
    const void*  __restrict__ eidx,
    const float* __restrict__ W2,   // [128]
    const float* __restrict__ b2,
    float* __restrict__ out,
    int E)
{
    const int lane = threadIdx.x & 31;
    const int warp = blockIdx.x * (blockDim.x >> 5) + (threadIdx.x >> 5);
    const long long e0 = (long long)warp * 4;
    if (e0 >= E) return;

    const float4 w2v = ((const float4*)W2)[lane];   // features 4*lane .. 4*lane+3
    const float  bias = b2[0];
    const int    is64 = g_idx_is64;
    const uint2* __restrict__ uvq = (const uint2*)g_uv;  // 4 halves per uint2; 64 per node row

    int rows[4], cols[4];
    #pragma unroll
    for (int t = 0; t < 4; ++t) {
        long long e = e0 + t;
        long long ec = (e < E) ? e : e0;
        if (is64) {
            rows[t] = (int)((const long long*)eidx)[ec];
            cols[t] = (int)((const long long*)eidx)[(long long)E + ec];
        } else {
            rows[t] = ((const int*)eidx)[ec];
            cols[t] = ((const int*)eidx)[(long long)E + ec];
        }
    }

    uint2 u[4], v[4];
    #pragma unroll
    for (int t = 0; t < 4; ++t) {
        u[t] = uvq[(long long)rows[t] * 64 + lane];        // u half: features 4*lane..+3
        v[t] = uvq[(long long)cols[t] * 64 + 32 + lane];   // v half
    }

    #pragma unroll
    for (int t = 0; t < 4; ++t) {
        float2 ua = bits_f2(u[t].x);
        float2 ub = bits_f2(u[t].y);
        float2 va = bits_f2(v[t].x);
        float2 vb = bits_f2(v[t].y);
        float s;
        s = fmaxf(ua.x + va.x, 0.f) * w2v.x;
        s = fmaf(fmaxf(ua.y + va.y, 0.f), w2v.y, s);
        s = fmaf(fmaxf(ub.x + vb.x, 0.f), w2v.z, s);
        s = fmaf(fmaxf(ub.y + vb.y, 0.f), w2v.w, s);
        s += __shfl_xor_sync(0xffffffffu, s, 16);
        s += __shfl_xor_sync(0xffffffffu, s, 8);
        s += __shfl_xor_sync(0xffffffffu, s, 4);
        s += __shfl_xor_sync(0xffffffffu, s, 2);
        s += __shfl_xor_sync(0xffffffffu, s, 1);
        if (lane == 0 && e0 + t < E) out[e0 + t] = s + bias;
    }
}

extern "C" void kernel_launch(void* const* d_in, const int* in_sizes, int n_in,
                              void* d_out, int out_size)
{
    const float* x   = (const float*)d_in[0];
    const void*  ei  = d_in[1];
    const float* W1  = (const float*)d_in[2];
    const float* b1  = (const float*)d_in[3];
    const float* W2  = (const float*)d_in[4];
    const float* b2  = (const float*)d_in[5];
    float* out = (float*)d_out;

    int n_nodes = in_sizes[0] / 128;
    int E = in_sizes[1] / 2;

    detect_idx_dtype<<<1, 32>>>(ei, n_nodes);

    dim3 pgrid((n_nodes + PT_M - 1) / PT_M, 2);
    precompute_uv<<<pgrid, NT>>>(x, W1, b1, n_nodes);

    long long warps = ((long long)E + 3) / 4;
    int blocks = (int)((warps + 7) / 8);
    edge_eval<<<blocks, 256>>>(ei, W2, b2, out, E);
}

// round 7
// speedup vs baseline: 12.2138x; 1.5103x over previous
#include <cuda_runtime.h>
#include <cuda_fp16.h>

// LinearEdgeDecoder, factored + fp16 table + HMMA precompute (static smem only):
//   uv[n][0:128]   = fp16( x[n] @ W1[0:128,:] + b1 )   (u)
//   uv[n][128:256] = fp16( x[n] @ W1[128:256,:] )      (v)
//   out[e] = relu(f32(u[row[e]]) + f32(v[col[e]])) . W2 + b2
//
// Precompute: mma.sync m16n8k16 fp16->fp32, CTA tile 128x128, K=128 in two
// 64-wide chunks. A chunk = [128 nodes][64 k], B chunk = [64 k][128 n]
// (R6 bug: B loader chunked W1's n-columns as k -- fixed: chunk W1 ROWS).
// Edge phase: 768MB L2-resident gather, 8 edges/warp (MLP=16).

#define ASK  72             // A chunk stride in halves (144B rows)
#define BSK  136            // B chunk stride in halves (272B rows)
#define AST  136            // staging stride in halves
#define NT   256

__device__ int    g_idx_is64;
__device__ __half g_uv[(size_t)131072 * 256];   // static scratch (no allocs allowed)

__device__ __forceinline__ unsigned h2_bits(__half2 h) {
    return *reinterpret_cast<unsigned*>(&h);
}
__device__ __forceinline__ float2 bits_f2(unsigned b) {
    return __half22float2(*reinterpret_cast<__half2*>(&b));
}

__device__ __forceinline__ void ldsm_x4(unsigned& r0, unsigned& r1, unsigned& r2, unsigned& r3,
                                        unsigned addr) {
    asm volatile("ldmatrix.sync.aligned.m8n8.x4.shared.b16 {%0,%1,%2,%3}, [%4];"
                 : "=r"(r0), "=r"(r1), "=r"(r2), "=r"(r3) : "r"(addr));
}
__device__ __forceinline__ void ldsm_x4_t(unsigned& r0, unsigned& r1, unsigned& r2, unsigned& r3,
                                          unsigned addr) {
    asm volatile("ldmatrix.sync.aligned.m8n8.x4.trans.shared.b16 {%0,%1,%2,%3}, [%4];"
                 : "=r"(r0), "=r"(r1), "=r"(r2), "=r"(r3) : "r"(addr));
}
__device__ __forceinline__ void mma16816(float* c, const unsigned* a, unsigned b0, unsigned b1) {
    asm volatile(
        "mma.sync.aligned.m16n8k16.row.col.f32.f16.f16.f32 "
        "{%0,%1,%2,%3},{%4,%5,%6,%7},{%8,%9},{%0,%1,%2,%3};"
        : "+f"(c[0]), "+f"(c[1]), "+f"(c[2]), "+f"(c[3])
        : "r"(a[0]), "r"(a[1]), "r"(a[2]), "r"(a[3]), "r"(b0), "r"(b1));
}

// ---------------- node-table GEMM on tensor cores ----------------
// grid = (ceil(n_nodes/128), 2). CTA tile 128 nodes x 128 features, K=128 in 2 chunks.
__global__ __launch_bounds__(NT) void precompute_uv(
    const float* __restrict__ x,    // [n_nodes, 128]
    const void*  __restrict__ eidx, // only for merged dtype detection
    const float* __restrict__ W1,   // [256, 128]  (k-major rows, n columns)
    const float* __restrict__ b1,   // [128]
    int n_nodes)
{
    // static pool: A chunk (128*72) + B chunk (64*136) = 17920 halves = 35840 B.
    // Reused whole as epilogue staging (128*136 = 17408 halves).
    __shared__ __align__(16) __half smem_s[128 * ASK + 64 * BSK];
    __half* sA = smem_s;
    __half* sB = smem_s + 128 * ASK;

    const int tid  = threadIdx.x;
    const int base = blockIdx.x * 128;
    const int half = blockIdx.y;     // 0 -> u (+b1), 1 -> v

    // merged index-dtype detection (one warp, one block)
    if (blockIdx.x == 0 && half == 0 && tid < 32) {
        const long long* p = (const long long*)eidx;
        int bad = 0;
        #pragma unroll
        for (int t = 0; t < 2; ++t) {
            long long vv = p[tid * 2 + t];
            if (vv < 0 || vv >= (long long)n_nodes) bad = 1;
        }
        unsigned m = __ballot_sync(0xffffffffu, bad);
        if (tid == 0) g_idx_is64 = (m == 0u);
    }

    const float4* __restrict__ x4 = (const float4*)x;
    const float4* __restrict__ w4 = (const float4*)W1;

    // A loader coords: thread = (node row rA 0..127, 32-float segment sA_ 0/1)
    const int rA  = tid >> 1;
    const int sA_ = tid & 1;
    int nodeA = base + rA; if (nodeA >= n_nodes) nodeA = 0;

    // B loader coords: thread = (k row rB 0..63, 32-float segment sB_ 0..3)
    const int rB  = tid >> 2;
    const int sB_ = tid & 3;

    // warp/mma coords
    const int w    = tid >> 5;
    const int lane = tid & 31;
    const int mw   = (w & 1) * 64;       // warp m offset
    const int nw   = (w >> 1) * 32;      // warp n offset
    const int lr   = lane & 15;
    const int lc   = (lane >> 4) * 8;

    float acc[4][4][4];
    #pragma unroll
    for (int i = 0; i < 4; ++i)
        #pragma unroll
        for (int j = 0; j < 4; ++j)
            #pragma unroll
            for (int t = 0; t < 4; ++t) acc[i][j][t] = 0.f;

    const unsigned sA0 = (unsigned)__cvta_generic_to_shared(sA);
    const unsigned sB0 = (unsigned)__cvta_generic_to_shared(sB);

    #pragma unroll
    for (int kc = 0; kc < 2; ++kc) {
        // ---- A chunk: x[node][kc*64 .. +64) -> sA[node][k_local] ----
        #pragma unroll
        for (int q = 0; q < 8; ++q) {
            float4 f = x4[(long long)nodeA * 32 + kc * 16 + sA_ * 8 + q];
            uint2 pk;
            pk.x = h2_bits(__floats2half2_rn(f.x, f.y));
            pk.y = h2_bits(__floats2half2_rn(f.z, f.w));
            *(uint2*)(sA + rA * ASK + sA_ * 32 + q * 4) = pk;
        }
        // ---- B chunk: W1 rows [half*128 + kc*64 .. +64), all 128 n-cols ----
        //      -> sB[k_local][n]
        #pragma unroll
        for (int q = 0; q < 8; ++q) {
            float4 f = w4[(long long)(half * 128 + kc * 64 + rB) * 32 + sB_ * 8 + q];
            uint2 pk;
            pk.x = h2_bits(__floats2half2_rn(f.x, f.y));
            pk.y = h2_bits(__floats2half2_rn(f.z, f.w));
            *(uint2*)(sB + rB * BSK + sB_ * 32 + q * 4) = pk;
        }
        __syncthreads();

        // ---- 4 k16 steps per chunk ----
        #pragma unroll
        for (int ks = 0; ks < 4; ++ks) {
            const int k0 = ks * 16;
            unsigned a[4][4];
            #pragma unroll
            for (int mt = 0; mt < 4; ++mt) {
                unsigned addr = sA0 + ((mw + mt * 16 + lr) * ASK + k0 + lc) * 2;
                ldsm_x4(a[mt][0], a[mt][1], a[mt][2], a[mt][3], addr);
            }
            unsigned b[4][2];
            #pragma unroll
            for (int pr = 0; pr < 2; ++pr) {
                unsigned addr = sB0 + ((k0 + lr) * BSK + nw + pr * 16 + lc) * 2;
                unsigned r0, r1, r2, r3;
                ldsm_x4_t(r0, r1, r2, r3, addr);
                b[pr * 2][0] = r0;     b[pr * 2][1] = r1;
                b[pr * 2 + 1][0] = r2; b[pr * 2 + 1][1] = r3;
            }
            #pragma unroll
            for (int mt = 0; mt < 4; ++mt)
                #pragma unroll
                for (int nt = 0; nt < 4; ++nt)
                    mma16816(acc[mt][nt], a[mt], b[nt][0], b[nt][1]);
        }
        __syncthreads();
    }

    // ---- epilogue: +b1 (u half), fp16, stage through smem, coalesced copy ----
    const int g  = lane >> 2;
    const int t2 = (lane & 3) * 2;
    float bx[4], by[4];
    #pragma unroll
    for (int nt = 0; nt < 4; ++nt) {
        int c0 = nw + nt * 8 + t2;
        bx[nt] = (half == 0) ? b1[c0]     : 0.f;
        by[nt] = (half == 0) ? b1[c0 + 1] : 0.f;
    }

    __half* stage = smem_s;
    #pragma unroll
    for (int mt = 0; mt < 4; ++mt) {
        #pragma unroll
        for (int nt = 0; nt < 4; ++nt) {
            int row = mw + mt * 16 + g;
            int col = nw + nt * 8 + t2;
            *(__half2*)(stage + row * AST + col) =
                __floats2half2_rn(acc[mt][nt][0] + bx[nt], acc[mt][nt][1] + by[nt]);
            *(__half2*)(stage + (row + 8) * AST + col) =
                __floats2half2_rn(acc[mt][nt][2] + bx[nt], acc[mt][nt][3] + by[nt]);
        }
    }
    __syncthreads();

    // copy 128 rows x 128 halves to g_uv: warp w owns rows [w*16, w*16+16)
    #pragma unroll
    for (int rr = 0; rr < 4; ++rr) {
        int r = w * 16 + rr * 4 + (lane >> 3);
        int node = base + r;
        if (node < n_nodes) {
            #pragma unroll
            for (int it = 0; it < 2; ++it) {
                int idx = (lane & 7) + it * 8;       // 16 uint4 per row
                uint4 val = *(uint4*)(stage + r * AST + idx * 8);
                *(uint4*)(g_uv + (size_t)node * 256 + half * 128 + idx * 8) = val;
            }
        }
    }
}

// ---------------- edge phase: fp16 gather-add-relu-dot, 8 edges/warp ----------------
__global__ __launch_bounds__(256) void edge_eval(
    const void*  __restrict__ eidx,
    const float* __restrict__ W2,   // [128]
    const float* __restrict__ b2,
    float* __restrict__ out,
    int E)
{
    const int lane = threadIdx.x & 31;
    const int warp = blockIdx.x * (blockDim.x >> 5) + (threadIdx.x >> 5);
    const long long e0 = (long long)warp * 8;
    if (e0 >= E) return;

    const float4 w2v = ((const float4*)W2)[lane];   // features 4*lane .. 4*lane+3
    const float  bias = b2[0];
    const int    is64 = g_idx_is64;
    const uint2* __restrict__ uvq = (const uint2*)g_uv;  // 4 halves per uint2; 64 per node row

    int rows[8], cols[8];
    #pragma unroll
    for (int t = 0; t < 8; ++t) {
        long long e = e0 + t;
        long long ec = (e < E) ? e : e0;
        if (is64) {
            rows[t] = (int)((const long long*)eidx)[ec];
            cols[t] = (int)((const long long*)eidx)[(long long)E + ec];
        } else {
            rows[t] = ((const int*)eidx)[ec];
            cols[t] = ((const int*)eidx)[(long long)E + ec];
        }
    }

    uint2 u[8], v[8];
    #pragma unroll
    for (int t = 0; t < 8; ++t) {
        u[t] = uvq[(long long)rows[t] * 64 + lane];        // u half
        v[t] = uvq[(long long)cols[t] * 64 + 32 + lane];   // v half
    }

    #pragma unroll
    for (int t = 0; t < 8; ++t) {
        float2 ua = bits_f2(u[t].x);
        float2 ub = bits_f2(u[t].y);
        float2 va = bits_f2(v[t].x);
        float2 vb = bits_f2(v[t].y);
        float s;
        s = fmaxf(ua.x + va.x, 0.f) * w2v.x;
        s = fmaf(fmaxf(ua.y + va.y, 0.f), w2v.y, s);
        s = fmaf(fmaxf(ub.x + vb.x, 0.f), w2v.z, s);
        s = fmaf(fmaxf(ub.y + vb.y, 0.f), w2v.w, s);
        s += __shfl_xor_sync(0xffffffffu, s, 16);
        s += __shfl_xor_sync(0xffffffffu, s, 8);
        s += __shfl_xor_sync(0xffffffffu, s, 4);
        s += __shfl_xor_sync(0xffffffffu, s, 2);
        s += __shfl_xor_sync(0xffffffffu, s, 1);
        if (lane == 0 && e0 + t < E) out[e0 + t] = s + bias;
    }
}

extern "C" void kernel_launch(void* const* d_in, const int* in_sizes, int n_in,
                              void* d_out, int out_size)
{
    const float* x   = (const float*)d_in[0];
    const void*  ei  = d_in[1];
    const float* W1  = (const float*)d_in[2];
    const float* b1  = (const float*)d_in[3];
    const float* W2  = (const float*)d_in[4];
    const float* b2  = (const float*)d_in[5];
    float* out = (float*)d_out;

    int n_nodes = in_sizes[0] / 128;
    int E = in_sizes[1] / 2;

    dim3 pgrid((n_nodes + 127) / 128, 2);
    precompute_uv<<<pgrid, NT>>>(x, ei, W1, b1, n_nodes);

    long long warps = ((long long)E + 7) / 8;
    int blocks = (int)((warps + 7) / 8);
    edge_eval<<<blocks, 256>>>(ei, W2, b2, out, E);
}

// round 8
// speedup vs baseline: 15.4985x; 1.2689x over previous
#include <cuda_runtime.h>
#include <cuda_fp16.h>

// LinearEdgeDecoder, factored + fp16 table + HMMA precompute:
//   uv[n][0:128]   = fp16( x[n] @ W1[0:128,:] + b1 )   (u)
//   uv[n][128:256] = fp16( x[n] @ W1[128:256,:] )      (v)
//   out[e] = relu(u[row[e]] + v[col[e]]) . W2 + b2
//
// R8: edge_eval rewritten for issue-bound profile (ncu: issue 79%, alu 53%):
//   - value-splitting multi-edge reduction: 9 shuffles per 8 edges (was 40)
//   - half2 add+relu (HADD2/HMAX2), f32 only for the W2 FMAs
//   - vectorized uniform index loads (int4 / longlong2)

#define ASK  72             // A chunk stride in halves (144B rows)
#define BSK  136            // B chunk stride in halves (272B rows)
#define AST  136            // staging stride in halves
#define NT   256

__device__ int    g_idx_is64;
__device__ __half g_uv[(size_t)131072 * 256];   // static scratch (no allocs allowed)

__device__ __forceinline__ unsigned h2_bits(__half2 h) {
    return *reinterpret_cast<unsigned*>(&h);
}
__device__ __forceinline__ __half2 bits_h2(unsigned b) {
    return *reinterpret_cast<__half2*>(&b);
}

__device__ __forceinline__ void ldsm_x4(unsigned& r0, unsigned& r1, unsigned& r2, unsigned& r3,
                                        unsigned addr) {
    asm volatile("ldmatrix.sync.aligned.m8n8.x4.shared.b16 {%0,%1,%2,%3}, [%4];"
                 : "=r"(r0), "=r"(r1), "=r"(r2), "=r"(r3) : "r"(addr));
}
__device__ __forceinline__ void ldsm_x4_t(unsigned& r0, unsigned& r1, unsigned& r2, unsigned& r3,
                                          unsigned addr) {
    asm volatile("ldmatrix.sync.aligned.m8n8.x4.trans.shared.b16 {%0,%1,%2,%3}, [%4];"
                 : "=r"(r0), "=r"(r1), "=r"(r2), "=r"(r3) : "r"(addr));
}
__device__ __forceinline__ void mma16816(float* c, const unsigned* a, unsigned b0, unsigned b1) {
    asm volatile(
        "mma.sync.aligned.m16n8k16.row.col.f32.f16.f16.f32 "
        "{%0,%1,%2,%3},{%4,%5,%6,%7},{%8,%9},{%0,%1,%2,%3};"
        : "+f"(c[0]), "+f"(c[1]), "+f"(c[2]), "+f"(c[3])
        : "r"(a[0]), "r"(a[1]), "r"(a[2]), "r"(a[3]), "r"(b0), "r"(b1));
}

// ---------------- node-table GEMM on tensor cores (unchanged from R7) ----------------
__global__ __launch_bounds__(NT) void precompute_uv(
    const float* __restrict__ x,    // [n_nodes, 128]
    const void*  __restrict__ eidx, // only for merged dtype detection
    const float* __restrict__ W1,   // [256, 128]
    const float* __restrict__ b1,   // [128]
    int n_nodes)
{
    __shared__ __align__(16) __half smem_s[128 * ASK + 64 * BSK];
    __half* sA = smem_s;
    __half* sB = smem_s + 128 * ASK;

    const int tid  = threadIdx.x;
    const int base = blockIdx.x * 128;
    const int half = blockIdx.y;     // 0 -> u (+b1), 1 -> v

    if (blockIdx.x == 0 && half == 0 && tid < 32) {
        const long long* p = (const long long*)eidx;
        int bad = 0;
        #pragma unroll
        for (int t = 0; t < 2; ++t) {
            long long vv = p[tid * 2 + t];
            if (vv < 0 || vv >= (long long)n_nodes) bad = 1;
        }
        unsigned m = __ballot_sync(0xffffffffu, bad);
        if (tid == 0) g_idx_is64 = (m == 0u);
    }

    const float4* __restrict__ x4 = (const float4*)x;
    const float4* __restrict__ w4 = (const float4*)W1;

    const int rA  = tid >> 1;
    const int sA_ = tid & 1;
    int nodeA = base + rA; if (nodeA >= n_nodes) nodeA = 0;

    const int rB  = tid >> 2;
    const int sB_ = tid & 3;

    const int w    = tid >> 5;
    const int lane = tid & 31;
    const int mw   = (w & 1) * 64;
    const int nw   = (w >> 1) * 32;
    const int lr   = lane & 15;
    const int lc   = (lane >> 4) * 8;

    float acc[4][4][4];
    #pragma unroll
    for (int i = 0; i < 4; ++i)
        #pragma unroll
        for (int j = 0; j < 4; ++j)
            #pragma unroll
            for (int t = 0; t < 4; ++t) acc[i][j][t] = 0.f;

    const unsigned sA0 = (unsigned)__cvta_generic_to_shared(sA);
    const unsigned sB0 = (unsigned)__cvta_generic_to_shared(sB);

    #pragma unroll
    for (int kc = 0; kc < 2; ++kc) {
        #pragma unroll
        for (int q = 0; q < 8; ++q) {
            float4 f = x4[(long long)nodeA * 32 + kc * 16 + sA_ * 8 + q];
            uint2 pk;
            pk.x = h2_bits(__floats2half2_rn(f.x, f.y));
            pk.y = h2_bits(__floats2half2_rn(f.z, f.w));
            *(uint2*)(sA + rA * ASK + sA_ * 32 + q * 4) = pk;
        }
        #pragma unroll
        for (int q = 0; q < 8; ++q) {
            float4 f = w4[(long long)(half * 128 + kc * 64 + rB) * 32 + sB_ * 8 + q];
            uint2 pk;
            pk.x = h2_bits(__floats2half2_rn(f.x, f.y));
            pk.y = h2_bits(__floats2half2_rn(f.z, f.w));
            *(uint2*)(sB + rB * BSK + sB_ * 32 + q * 4) = pk;
        }
        __syncthreads();

        #pragma unroll
        for (int ks = 0; ks < 4; ++ks) {
            const int k0 = ks * 16;
            unsigned a[4][4];
            #pragma unroll
            for (int mt = 0; mt < 4; ++mt) {
                unsigned addr = sA0 + ((mw + mt * 16 + lr) * ASK + k0 + lc) * 2;
                ldsm_x4(a[mt][0], a[mt][1], a[mt][2], a[mt][3], addr);
            }
            unsigned b[4][2];
            #pragma unroll
            for (int pr = 0; pr < 2; ++pr) {
                unsigned addr = sB0 + ((k0 + lr) * BSK + nw + pr * 16 + lc) * 2;
                unsigned r0, r1, r2, r3;
                ldsm_x4_t(r0, r1, r2, r3, addr);
                b[pr * 2][0] = r0;     b[pr * 2][1] = r1;
                b[pr * 2 + 1][0] = r2; b[pr * 2 + 1][1] = r3;
            }
            #pragma unroll
            for (int mt = 0; mt < 4; ++mt)
                #pragma unroll
                for (int nt = 0; nt < 4; ++nt)
                    mma16816(acc[mt][nt], a[mt], b[nt][0], b[nt][1]);
        }
        __syncthreads();
    }

    const int g  = lane >> 2;
    const int t2 = (lane & 3) * 2;
    float bx[4], by[4];
    #pragma unroll
    for (int nt = 0; nt < 4; ++nt) {
        int c0 = nw + nt * 8 + t2;
        bx[nt] = (half == 0) ? b1[c0]     : 0.f;
        by[nt] = (half == 0) ? b1[c0 + 1] : 0.f;
    }

    __half* stage = smem_s;
    #pragma unroll
    for (int mt = 0; mt < 4; ++mt) {
        #pragma unroll
        for (int nt = 0; nt < 4; ++nt) {
            int row = mw + mt * 16 + g;
            int col = nw + nt * 8 + t2;
            *(__half2*)(stage + row * AST + col) =
                __floats2half2_rn(acc[mt][nt][0] + bx[nt], acc[mt][nt][1] + by[nt]);
            *(__half2*)(stage + (row + 8) * AST + col) =
                __floats2half2_rn(acc[mt][nt][2] + bx[nt], acc[mt][nt][3] + by[nt]);
        }
    }
    __syncthreads();

    #pragma unroll
    for (int rr = 0; rr < 4; ++rr) {
        int r = w * 16 + rr * 4 + (lane >> 3);
        int node = base + r;
        if (node < n_nodes) {
            #pragma unroll
            for (int it = 0; it < 2; ++it) {
                int idx = (lane & 7) + it * 8;
                uint4 val = *(uint4*)(stage + r * AST + idx * 8);
                *(uint4*)(g_uv + (size_t)node * 256 + half * 128 + idx * 8) = val;
            }
        }
    }
}

// ---------------- edge phase v2: issue-optimized ----------------
__global__ __launch_bounds__(256) void edge_eval(
    const void*  __restrict__ eidx,
    const float* __restrict__ W2,   // [128]
    const float* __restrict__ b2,
    float* __restrict__ out,
    int E)
{
    const int lane = threadIdx.x & 31;
    const int warp = blockIdx.x * 8 + (threadIdx.x >> 5);
    const long long e0 = (long long)warp * 8;
    if (e0 >= E) return;

    const float4 w2v = ((const float4*)W2)[lane];   // features 4*lane..+3
    const float  bias = b2[0];
    const int    is64 = g_idx_is64;
    const uint2* __restrict__ uvq = (const uint2*)g_uv;  // 4 halves; 64 per node row

    int rows[8], cols[8];
    const bool full = (e0 + 8 <= E) && ((E & 7) == 0);
    if (full) {
        if (is64) {
            const longlong2* rp = (const longlong2*)eidx;
            #pragma unroll
            for (int q = 0; q < 4; ++q) {
                longlong2 rr = rp[(e0 >> 1) + q];
                rows[q * 2] = (int)rr.x; rows[q * 2 + 1] = (int)rr.y;
                longlong2 cc = rp[(((long long)E + e0) >> 1) + q];
                cols[q * 2] = (int)cc.x; cols[q * 2 + 1] = (int)cc.y;
            }
        } else {
            const int4* rp = (const int4*)eidx;
            int4 ra = rp[e0 >> 2], rb = rp[(e0 >> 2) + 1];
            int4 ca = rp[((long long)E + e0) >> 2], cb = rp[(((long long)E + e0) >> 2) + 1];
            rows[0]=ra.x; rows[1]=ra.y; rows[2]=ra.z; rows[3]=ra.w;
            rows[4]=rb.x; rows[5]=rb.y; rows[6]=rb.z; rows[7]=rb.w;
            cols[0]=ca.x; cols[1]=ca.y; cols[2]=ca.z; cols[3]=ca.w;
            cols[4]=cb.x; cols[5]=cb.y; cols[6]=cb.z; cols[7]=cb.w;
        }
    } else {
        #pragma unroll
        for (int t = 0; t < 8; ++t) {
            long long e = e0 + t;
            long long ec = (e < E) ? e : e0;
            if (is64) {
                rows[t] = (int)((const long long*)eidx)[ec];
                cols[t] = (int)((const long long*)eidx)[(long long)E + ec];
            } else {
                rows[t] = ((const int*)eidx)[ec];
                cols[t] = ((const int*)eidx)[(long long)E + ec];
            }
        }
    }

    uint2 u[8], v[8];
    #pragma unroll
    for (int t = 0; t < 8; ++t) {
        u[t] = uvq[(long long)rows[t] * 64 + lane];
        v[t] = uvq[(long long)cols[t] * 64 + 32 + lane];
    }

    const __half2 z2 = __float2half2_rn(0.f);
    float s[8];
    #pragma unroll
    for (int t = 0; t < 8; ++t) {
        __half2 h0 = __hmax2(__hadd2(bits_h2(u[t].x), bits_h2(v[t].x)), z2);
        __half2 h1 = __hmax2(__hadd2(bits_h2(u[t].y), bits_h2(v[t].y)), z2);
        float2 f0 = __half22float2(h0);
        float2 f1 = __half22float2(h1);
        float r;
        r = f0.x * w2v.x;
        r = fmaf(f0.y, w2v.y, r);
        r = fmaf(f1.x, w2v.z, r);
        r = fmaf(f1.y, w2v.w, r);
        s[t] = r;
    }

    // value-splitting reduction across 32 lanes, 8 edges jointly
    const unsigned FULLM = 0xffffffffu;
    const bool hi16 = (lane & 16);
    float a[4];
    #pragma unroll
    for (int t = 0; t < 4; ++t) {
        float send = hi16 ? s[t] : s[t + 4];
        float recv = __shfl_xor_sync(FULLM, send, 16);
        a[t] = (hi16 ? s[t + 4] : s[t]) + recv;
    }
    const bool hi8 = (lane & 8);
    float b[2];
    #pragma unroll
    for (int t = 0; t < 2; ++t) {
        float send = hi8 ? a[t] : a[t + 2];
        float recv = __shfl_xor_sync(FULLM, send, 8);
        b[t] = (hi8 ? a[t + 2] : a[t]) + recv;
    }
    const bool hi4 = (lane & 4);
    float c;
    {
        float send = hi4 ? b[0] : b[1];
        float recv = __shfl_xor_sync(FULLM, send, 4);
        c = (hi4 ? b[1] : b[0]) + recv;
    }
    c += __shfl_xor_sync(FULLM, c, 2);
    c += __shfl_xor_sync(FULLM, c, 1);

    // lane bits (4,3,2) -> edge id
    int eid = ((lane >> 2) & 1) | ((lane >> 2) & 2) | ((lane >> 2) & 4);
    eid = (((lane >> 4) & 1) << 2) | (((lane >> 3) & 1) << 1) | ((lane >> 2) & 1);
    if ((lane & 3) == 0) {
        long long e = e0 + eid;
        if (e < E) out[e] = c + bias;
    }
}

extern "C" void kernel_launch(void* const* d_in, const int* in_sizes, int n_in,
                              void* d_out, int out_size)
{
    const float* x   = (const float*)d_in[0];
    const void*  ei  = d_in[1];
    const float* W1  = (const float*)d_in[2];
    const float* b1  = (const float*)d_in[3];
    const float* W2  = (const float*)d_in[4];
    const float* b2  = (const float*)d_in[5];
    float* out = (float*)d_out;

    int n_nodes = in_sizes[0] / 128;
    int E = in_sizes[1] / 2;

    dim3 pgrid((n_nodes + 127) / 128, 2);
    precompute_uv<<<pgrid, NT>>>(x, ei, W1, b1, n_nodes);

    long long warps = ((long long)E + 7) / 8;
    int blocks = (int)((warps + 7) / 8);
    edge_eval<<<blocks, 256>>>(ei, W2, b2, out, E);
}

// round 9
// speedup vs baseline: 19.1636x; 1.2365x over previous
#include <cuda_runtime.h>
#include <cuda_fp16.h>

// LinearEdgeDecoder, factored + fp16 table + HMMA precompute.
// R9: (a) one-shot fp16 conversion of x and W1 into static buffers -- precompute
// loses all cvt + half its load/STS instructions; (b) edge phase uses 16
// lanes/edge with uint4 gathers (half the LDG/address instructions).

#define ASK  72             // A chunk stride in halves (144B rows)
#define BSK  136            // B chunk stride in halves (272B rows)
#define AST  136            // staging stride in halves
#define NT   256

__device__ int    g_idx_is64;
__device__ __half g_uv[(size_t)131072 * 256];   // node table u|v (64 MB)
__device__ __half g_xh[(size_t)131072 * 128];   // x in fp16 (32 MB)
__device__ __half g_wh[256 * 128];              // W1 in fp16

__device__ __forceinline__ unsigned h2_bits(__half2 h) {
    return *reinterpret_cast<unsigned*>(&h);
}
__device__ __forceinline__ __half2 bits_h2(unsigned b) {
    return *reinterpret_cast<__half2*>(&b);
}

__device__ __forceinline__ void ldsm_x4(unsigned& r0, unsigned& r1, unsigned& r2, unsigned& r3,
                                        unsigned addr) {
    asm volatile("ldmatrix.sync.aligned.m8n8.x4.shared.b16 {%0,%1,%2,%3}, [%4];"
                 : "=r"(r0), "=r"(r1), "=r"(r2), "=r"(r3) : "r"(addr));
}
__device__ __forceinline__ void ldsm_x4_t(unsigned& r0, unsigned& r1, unsigned& r2, unsigned& r3,
                                          unsigned addr) {
    asm volatile("ldmatrix.sync.aligned.m8n8.x4.trans.shared.b16 {%0,%1,%2,%3}, [%4];"
                 : "=r"(r0), "=r"(r1), "=r"(r2), "=r"(r3) : "r"(addr));
}
__device__ __forceinline__ void mma16816(float* c, const unsigned* a, unsigned b0, unsigned b1) {
    asm volatile(
        "mma.sync.aligned.m16n8k16.row.col.f32.f16.f16.f32 "
        "{%0,%1,%2,%3},{%4,%5,%6,%7},{%8,%9},{%0,%1,%2,%3};"
        : "+f"(c[0]), "+f"(c[1]), "+f"(c[2]), "+f"(c[3])
        : "r"(a[0]), "r"(a[1]), "r"(a[2]), "r"(a[3]), "r"(b0), "r"(b1));
}

// ---------------- one-shot fp16 conversion (+ dtype sniff) ----------------
__global__ __launch_bounds__(256) void convert_fp16(
    const float* __restrict__ x,    // [n_nodes, 128]
    const float* __restrict__ W1,   // [256, 128]
    const void*  __restrict__ eidx,
    int n_nodes)
{
    long long i = (long long)blockIdx.x * 256 + threadIdx.x;

    if (blockIdx.x == 0 && threadIdx.x < 32) {
        const long long* p = (const long long*)eidx;
        int bad = 0;
        #pragma unroll
        for (int t = 0; t < 2; ++t) {
            long long vv = p[threadIdx.x * 2 + t];
            if (vv < 0 || vv >= (long long)n_nodes) bad = 1;
        }
        unsigned m = __ballot_sync(0xffffffffu, bad);
        if (threadIdx.x == 0) g_idx_is64 = (m == 0u);
    }

    long long total = (long long)n_nodes * 32;   // float4 count of x
    if (i < total) {
        float4 f = ((const float4*)x)[i];
        uint2 pk;
        pk.x = h2_bits(__floats2half2_rn(f.x, f.y));
        pk.y = h2_bits(__floats2half2_rn(f.z, f.w));
        ((uint2*)g_xh)[i] = pk;
    }
    if (i < 8192) {                              // W1 = 8192 float4
        float4 f = ((const float4*)W1)[i];
        uint2 pk;
        pk.x = h2_bits(__floats2half2_rn(f.x, f.y));
        pk.y = h2_bits(__floats2half2_rn(f.z, f.w));
        ((uint2*)g_wh)[i] = pk;
    }
}

// ---------------- node-table GEMM on tensor cores ----------------
// grid = (ceil(n_nodes/128), 2). CTA tile 128 nodes x 128 features, K=128 in 2 chunks.
__global__ __launch_bounds__(NT) void precompute_uv(
    const float* __restrict__ b1,   // [128]
    int n_nodes)
{
    __shared__ __align__(16) __half smem_s[128 * ASK + 64 * BSK];
    __half* sA = smem_s;
    __half* sB = smem_s + 128 * ASK;

    const int tid  = threadIdx.x;
    const int base = blockIdx.x * 128;
    const int half = blockIdx.y;     // 0 -> u (+b1), 1 -> v

    const int rA  = tid >> 1;
    const int sA_ = tid & 1;
    int nodeA = base + rA; if (nodeA >= n_nodes) nodeA = 0;

    const int rB  = tid >> 2;
    const int sB_ = tid & 3;

    const int w    = tid >> 5;
    const int lane = tid & 31;
    const int mw   = (w & 1) * 64;
    const int nw   = (w >> 1) * 32;
    const int lr   = lane & 15;
    const int lc   = (lane >> 4) * 8;

    float acc[4][4][4];
    #pragma unroll
    for (int i = 0; i < 4; ++i)
        #pragma unroll
        for (int j = 0; j < 4; ++j)
            #pragma unroll
            for (int t = 0; t < 4; ++t) acc[i][j][t] = 0.f;

    const unsigned sA0 = (unsigned)__cvta_generic_to_shared(sA);
    const unsigned sB0 = (unsigned)__cvta_generic_to_shared(sB);
    const uint4* __restrict__ xh4 = (const uint4*)g_xh;   // 16 per node row
    const uint4* __restrict__ wh4 = (const uint4*)g_wh;   // 16 per W1 row

    #pragma unroll
    for (int kc = 0; kc < 2; ++kc) {
        // A chunk: fp16 x rows, no conversion
        #pragma unroll
        for (int q = 0; q < 4; ++q) {
            uint4 val = xh4[(size_t)nodeA * 16 + kc * 8 + sA_ * 4 + q];
            *(uint4*)(sA + rA * ASK + sA_ * 32 + q * 8) = val;
        }
        // B chunk: fp16 W1 rows [half*128 + kc*64 .. +64)
        #pragma unroll
        for (int q = 0; q < 4; ++q) {
            uint4 val = wh4[(size_t)(half * 128 + kc * 64 + rB) * 16 + sB_ * 4 + q];
            *(uint4*)(sB + rB * BSK + sB_ * 32 + q * 8) = val;
        }
        __syncthreads();

        #pragma unroll
        for (int ks = 0; ks < 4; ++ks) {
            const int k0 = ks * 16;
            unsigned a[4][4];
            #pragma unroll
            for (int mt = 0; mt < 4; ++mt) {
                unsigned addr = sA0 + ((mw + mt * 16 + lr) * ASK + k0 + lc) * 2;
                ldsm_x4(a[mt][0], a[mt][1], a[mt][2], a[mt][3], addr);
            }
            unsigned b[4][2];
            #pragma unroll
            for (int pr = 0; pr < 2; ++pr) {
                unsigned addr = sB0 + ((k0 + lr) * BSK + nw + pr * 16 + lc) * 2;
                unsigned r0, r1, r2, r3;
                ldsm_x4_t(r0, r1, r2, r3, addr);
                b[pr * 2][0] = r0;     b[pr * 2][1] = r1;
                b[pr * 2 + 1][0] = r2; b[pr * 2 + 1][1] = r3;
            }
            #pragma unroll
            for (int mt = 0; mt < 4; ++mt)
                #pragma unroll
                for (int nt = 0; nt < 4; ++nt)
                    mma16816(acc[mt][nt], a[mt], b[nt][0], b[nt][1]);
        }
        __syncthreads();
    }

    // epilogue: +b1 (u half), fp16, stage through smem, coalesced copy
    const int g  = lane >> 2;
    const int t2 = (lane & 3) * 2;
    float bx[4], by[4];
    #pragma unroll
    for (int nt = 0; nt < 4; ++nt) {
        int c0 = nw + nt * 8 + t2;
        bx[nt] = (half == 0) ? b1[c0]     : 0.f;
        by[nt] = (half == 0) ? b1[c0 + 1] : 0.f;
    }

    __half* stage = smem_s;
    #pragma unroll
    for (int mt = 0; mt < 4; ++mt) {
        #pragma unroll
        for (int nt = 0; nt < 4; ++nt) {
            int row = mw + mt * 16 + g;
            int col = nw + nt * 8 + t2;
            *(__half2*)(stage + row * AST + col) =
                __floats2half2_rn(acc[mt][nt][0] + bx[nt], acc[mt][nt][1] + by[nt]);
            *(__half2*)(stage + (row + 8) * AST + col) =
                __floats2half2_rn(acc[mt][nt][2] + bx[nt], acc[mt][nt][3] + by[nt]);
        }
    }
    __syncthreads();

    #pragma unroll
    for (int rr = 0; rr < 4; ++rr) {
        int r = w * 16 + rr * 4 + (lane >> 3);
        int node = base + r;
        if (node < n_nodes) {
            #pragma unroll
            for (int it = 0; it < 2; ++it) {
                int idx = (lane & 7) + it * 8;
                uint4 val = *(uint4*)(stage + r * AST + idx * 8);
                *(uint4*)(g_uv + (size_t)node * 256 + half * 128 + idx * 8) = val;
            }
        }
    }
}

// ---------------- edge phase v3: 16 lanes/edge, uint4 gathers ----------------
__global__ __launch_bounds__(256) void edge_eval(
    const void*  __restrict__ eidx,
    const float* __restrict__ W2,   // [128]
    const float* __restrict__ b2,
    float* __restrict__ out,
    int E)
{
    const int lane = threadIdx.x & 31;
    const int hl   = lane & 15;       // halflane: feature group
    const int side = lane >> 4;       // which edge of each pair
    const int warp = blockIdx.x * 8 + (threadIdx.x >> 5);
    const long long e0 = (long long)warp * 8;
    if (e0 >= E) return;

    const float4 w2a = ((const float4*)W2)[hl * 2];      // features hl*8 .. +3
    const float4 w2b = ((const float4*)W2)[hl * 2 + 1];  // features hl*8+4 .. +7
    const float  bias = b2[0];
    const int    is64 = g_idx_is64;
    const uint4* __restrict__ uvq = (const uint4*)g_uv;  // 32 uint4 per node row

    // slot t covers edge e0 + 2t + side for this lane
    int nr[4], nc[4];
    if (e0 + 8 <= E && (E & 1) == 0) {
        if (is64) {
            const longlong2* rp = (const longlong2*)eidx;
            #pragma unroll
            for (int t = 0; t < 4; ++t) {
                longlong2 rr = rp[(e0 >> 1) + t];
                nr[t] = (int)(side ? rr.y : rr.x);
                longlong2 cc = rp[(((long long)E + e0) >> 1) + t];
                nc[t] = (int)(side ? cc.y : cc.x);
            }
        } else {
            const int2* rp = (const int2*)eidx;
            #pragma unroll
            for (int t = 0; t < 4; ++t) {
                int2 rr = rp[(e0 >> 1) + t];
                nr[t] = side ? rr.y : rr.x;
                int2 cc = rp[(((long long)E + e0) >> 1) + t];
                nc[t] = side ? cc.y : cc.x;
            }
        }
    } else {
        #pragma unroll
        for (int t = 0; t < 4; ++t) {
            long long e = e0 + 2 * t + side;
            if (e >= E) e = e0;
            if (is64) {
                nr[t] = (int)((const long long*)eidx)[e];
                nc[t] = (int)((const long long*)eidx)[(long long)E + e];
            } else {
                nr[t] = ((const int*)eidx)[e];
                nc[t] = ((const int*)eidx)[(long long)E + e];
            }
        }
    }

    uint4 u[4], v[4];
    #pragma unroll
    for (int t = 0; t < 4; ++t) {
        u[t] = uvq[(size_t)nr[t] * 32 + hl];         // u half: features hl*8..+7
        v[t] = uvq[(size_t)nc[t] * 32 + 16 + hl];    // v half
    }

    const __half2 z2 = __float2half2_rn(0.f);
    float s[4];
    #pragma unroll
    for (int t = 0; t < 4; ++t) {
        __half2 p0 = __hmax2(__hadd2(bits_h2(u[t].x), bits_h2(v[t].x)), z2);
        __half2 p1 = __hmax2(__hadd2(bits_h2(u[t].y), bits_h2(v[t].y)), z2);
        __half2 p2 = __hmax2(__hadd2(bits_h2(u[t].z), bits_h2(v[t].z)), z2);
        __half2 p3 = __hmax2(__hadd2(bits_h2(u[t].w), bits_h2(v[t].w)), z2);
        float2 f0 = __half22float2(p0);
        float2 f1 = __half22float2(p1);
        float2 f2 = __half22float2(p2);
        float2 f3 = __half22float2(p3);
        float r;
        r = f0.x * w2a.x;
        r = fmaf(f0.y, w2a.y, r);
        r = fmaf(f1.x, w2a.z, r);
        r = fmaf(f1.y, w2a.w, r);
        r = fmaf(f2.x, w2b.x, r);
        r = fmaf(f2.y, w2b.y, r);
        r = fmaf(f3.x, w2b.z, r);
        r = fmaf(f3.y, w2b.w, r);
        s[t] = r;
    }

    // value-splitting reduction over the 16 feature lanes (4 slots jointly)
    const unsigned FULLM = 0xffffffffu;
    const bool h8 = (hl & 8);
    float a0, a1;
    {
        float r0 = __shfl_xor_sync(FULLM, h8 ? s[0] : s[2], 8);
        a0 = (h8 ? s[2] : s[0]) + r0;
        float r1 = __shfl_xor_sync(FULLM, h8 ? s[1] : s[3], 8);
        a1 = (h8 ? s[3] : s[1]) + r1;
    }
    const bool h4 = (hl & 4);
    float b;
    {
        float r = __shfl_xor_sync(FULLM, h4 ? a0 : a1, 4);
        b = (h4 ? a1 : a0) + r;
    }
    b += __shfl_xor_sync(FULLM, b, 2);
    b += __shfl_xor_sync(FULLM, b, 1);

    // lane (h8,h4) -> slot; edge = e0 + 2*slot + side
    int slot = ((hl >> 3) & 1) * 2 + ((hl >> 2) & 1);
    if ((hl & 3) == 0) {
        long long e = e0 + 2 * slot + side;
        if (e < E) out[e] = b + bias;
    }
}

extern "C" void kernel_launch(void* const* d_in, const int* in_sizes, int n_in,
                              void* d_out, int out_size)
{
    const float* x   = (const float*)d_in[0];
    const void*  ei  = d_in[1];
    const float* W1  = (const float*)d_in[2];
    const float* b1  = (const float*)d_in[3];
    const float* W2  = (const float*)d_in[4];
    const float* b2  = (const float*)d_in[5];
    float* out = (float*)d_out;

    int n_nodes = in_sizes[0] / 128;
    int E = in_sizes[1] / 2;

    long long total4 = (long long)n_nodes * 32;
    int cblocks = (int)((total4 + 255) / 256);
    convert_fp16<<<cblocks, 256>>>(x, W1, ei, n_nodes);

    dim3 pgrid((n_nodes + 127) / 128, 2);
    precompute_uv<<<pgrid, NT>>>(b1, n_nodes);

    long long warps = ((long long)E + 7) / 8;
    int blocks = (int)((warps + 7) / 8);
    edge_eval<<<blocks, 256>>>(ei, W2, b2, out, E);
}

// round 11
// speedup vs baseline: 20.1559x; 1.0518x over previous
#include <cuda_runtime.h>
#include <cuda_fp16.h>

// LinearEdgeDecoder, factored + fp16 table + HMMA precompute.
// R11 (= R10 resubmit; prior run died to container flake, no kernel signal):
// edge phase W2 dot in fp16 (HFMA2 accumulation, W2 pre-converted) and
// 32-bit gather offset math -- ~40% fewer math ops in the issue-bound kernel.

#define ASK  72             // A chunk stride in halves (144B rows)
#define BSK  136            // B chunk stride in halves (272B rows)
#define AST  136            // staging stride in halves
#define NT   256

__device__ int    g_idx_is64;
__device__ __half g_uv[(size_t)131072 * 256];   // node table u|v (64 MB)
__device__ __half g_xh[(size_t)131072 * 128];   // x in fp16 (32 MB)
__device__ __half g_wh[256 * 128];              // W1 in fp16
__device__ __half g_w2h[128];                   // W2 in fp16

__device__ __forceinline__ unsigned h2_bits(__half2 h) {
    return *reinterpret_cast<unsigned*>(&h);
}
__device__ __forceinline__ __half2 bits_h2(unsigned b) {
    return *reinterpret_cast<__half2*>(&b);
}

__device__ __forceinline__ void ldsm_x4(unsigned& r0, unsigned& r1, unsigned& r2, unsigned& r3,
                                        unsigned addr) {
    asm volatile("ldmatrix.sync.aligned.m8n8.x4.shared.b16 {%0,%1,%2,%3}, [%4];"
                 : "=r"(r0), "=r"(r1), "=r"(r2), "=r"(r3) : "r"(addr));
}
__device__ __forceinline__ void ldsm_x4_t(unsigned& r0, unsigned& r1, unsigned& r2, unsigned& r3,
                                          unsigned addr) {
    asm volatile("ldmatrix.sync.aligned.m8n8.x4.trans.shared.b16 {%0,%1,%2,%3}, [%4];"
                 : "=r"(r0), "=r"(r1), "=r"(r2), "=r"(r3) : "r"(addr));
}
__device__ __forceinline__ void mma16816(float* c, const unsigned* a, unsigned b0, unsigned b1) {
    asm volatile(
        "mma.sync.aligned.m16n8k16.row.col.f32.f16.f16.f32 "
        "{%0,%1,%2,%3},{%4,%5,%6,%7},{%8,%9},{%0,%1,%2,%3};"
        : "+f"(c[0]), "+f"(c[1]), "+f"(c[2]), "+f"(c[3])
        : "r"(a[0]), "r"(a[1]), "r"(a[2]), "r"(a[3]), "r"(b0), "r"(b1));
}

// ---------------- one-shot fp16 conversion (+ dtype sniff) ----------------
__global__ __launch_bounds__(256) void convert_fp16(
    const float* __restrict__ x,    // [n_nodes, 128]
    const float* __restrict__ W1,   // [256, 128]
    const float* __restrict__ W2,   // [128]
    const void*  __restrict__ eidx,
    int n_nodes)
{
    long long i = (long long)blockIdx.x * 256 + threadIdx.x;

    if (blockIdx.x == 0 && threadIdx.x < 32) {
        const long long* p = (const long long*)eidx;
        int bad = 0;
        #pragma unroll
        for (int t = 0; t < 2; ++t) {
            long long vv = p[threadIdx.x * 2 + t];
            if (vv < 0 || vv >= (long long)n_nodes) bad = 1;
        }
        unsigned m = __ballot_sync(0xffffffffu, bad);
        if (threadIdx.x == 0) g_idx_is64 = (m == 0u);
    }

    long long total = (long long)n_nodes * 32;   // float4 count of x
    if (i < total) {
        float4 f = ((const float4*)x)[i];
        uint2 pk;
        pk.x = h2_bits(__floats2half2_rn(f.x, f.y));
        pk.y = h2_bits(__floats2half2_rn(f.z, f.w));
        ((uint2*)g_xh)[i] = pk;
    }
    if (i < 8192) {                              // W1 = 8192 float4
        float4 f = ((const float4*)W1)[i];
        uint2 pk;
        pk.x = h2_bits(__floats2half2_rn(f.x, f.y));
        pk.y = h2_bits(__floats2half2_rn(f.z, f.w));
        ((uint2*)g_wh)[i] = pk;
    }
    if (i < 32) {                                // W2 = 32 float4
        float4 f = ((const float4*)W2)[i];
        uint2 pk;
        pk.x = h2_bits(__floats2half2_rn(f.x, f.y));
        pk.y = h2_bits(__floats2half2_rn(f.z, f.w));
        ((uint2*)g_w2h)[i] = pk;
    }
}

// ---------------- node-table GEMM on tensor cores ----------------
// grid = (ceil(n_nodes/128), 2). CTA tile 128 nodes x 128 features, K=128 in 2 chunks.
__global__ __launch_bounds__(NT) void precompute_uv(
    const float* __restrict__ b1,   // [128]
    int n_nodes)
{
    __shared__ __align__(16) __half smem_s[128 * ASK + 64 * BSK];
    __half* sA = smem_s;
    __half* sB = smem_s + 128 * ASK;

    const int tid  = threadIdx.x;
    const int base = blockIdx.x * 128;
    const int half = blockIdx.y;     // 0 -> u (+b1), 1 -> v

    const int rA  = tid >> 1;
    const int sA_ = tid & 1;
    int nodeA = base + rA; if (nodeA >= n_nodes) nodeA = 0;

    const int rB  = tid >> 2;
    const int sB_ = tid & 3;

    const int w    = tid >> 5;
    const int lane = tid & 31;
    const int mw   = (w & 1) * 64;
    const int nw   = (w >> 1) * 32;
    const int lr   = lane & 15;
    const int lc   = (lane >> 4) * 8;

    float acc[4][4][4];
    #pragma unroll
    for (int i = 0; i < 4; ++i)
        #pragma unroll
        for (int j = 0; j < 4; ++j)
            #pragma unroll
            for (int t = 0; t < 4; ++t) acc[i][j][t] = 0.f;

    const unsigned sA0 = (unsigned)__cvta_generic_to_shared(sA);
    const unsigned sB0 = (unsigned)__cvta_generic_to_shared(sB);
    const uint4* __restrict__ xh4 = (const uint4*)g_xh;   // 16 per node row
    const uint4* __restrict__ wh4 = (const uint4*)g_wh;   // 16 per W1 row

    #pragma unroll
    for (int kc = 0; kc < 2; ++kc) {
        #pragma unroll
        for (int q = 0; q < 4; ++q) {
            uint4 val = xh4[(size_t)nodeA * 16 + kc * 8 + sA_ * 4 + q];
            *(uint4*)(sA + rA * ASK + sA_ * 32 + q * 8) = val;
        }
        #pragma unroll
        for (int q = 0; q < 4; ++q) {
            uint4 val = wh4[(size_t)(half * 128 + kc * 64 + rB) * 16 + sB_ * 4 + q];
            *(uint4*)(sB + rB * BSK + sB_ * 32 + q * 8) = val;
        }
        __syncthreads();

        #pragma unroll
        for (int ks = 0; ks < 4; ++ks) {
            const int k0 = ks * 16;
            unsigned a[4][4];
            #pragma unroll
            for (int mt = 0; mt < 4; ++mt) {
                unsigned addr = sA0 + ((mw + mt * 16 + lr) * ASK + k0 + lc) * 2;
                ldsm_x4(a[mt][0], a[mt][1], a[mt][2], a[mt][3], addr);
            }
            unsigned b[4][2];
            #pragma unroll
            for (int pr = 0; pr < 2; ++pr) {
                unsigned addr = sB0 + ((k0 + lr) * BSK + nw + pr * 16 + lc) * 2;
                unsigned r0, r1, r2, r3;
                ldsm_x4_t(r0, r1, r2, r3, addr);
                b[pr * 2][0] = r0;     b[pr * 2][1] = r1;
                b[pr * 2 + 1][0] = r2; b[pr * 2 + 1][1] = r3;
            }
            #pragma unroll
            for (int mt = 0; mt < 4; ++mt)
                #pragma unroll
                for (int nt = 0; nt < 4; ++nt)
                    mma16816(acc[mt][nt], a[mt], b[nt][0], b[nt][1]);
        }
        __syncthreads();
    }

    const int g  = lane >> 2;
    const int t2 = (lane & 3) * 2;
    float bx[4], by[4];
    #pragma unroll
    for (int nt = 0; nt < 4; ++nt) {
        int c0 = nw + nt * 8 + t2;
        bx[nt] = (half == 0) ? b1[c0]     : 0.f;
        by[nt] = (half == 0) ? b1[c0 + 1] : 0.f;
    }

    __half* stage = smem_s;
    #pragma unroll
    for (int mt = 0; mt < 4; ++mt) {
        #pragma unroll
        for (int nt = 0; nt < 4; ++nt) {
            int row = mw + mt * 16 + g;
            int col = nw + nt * 8 + t2;
            *(__half2*)(stage + row * AST + col) =
                __floats2half2_rn(acc[mt][nt][0] + bx[nt], acc[mt][nt][1] + by[nt]);
            *(__half2*)(stage + (row + 8) * AST + col) =
                __floats2half2_rn(acc[mt][nt][2] + bx[nt], acc[mt][nt][3] + by[nt]);
        }
    }
    __syncthreads();

    #pragma unroll
    for (int rr = 0; rr < 4; ++rr) {
        int r = w * 16 + rr * 4 + (lane >> 3);
        int node = base + r;
        if (node < n_nodes) {
            #pragma unroll
            for (int it = 0; it < 2; ++it) {
                int idx = (lane & 7) + it * 8;
                uint4 val = *(uint4*)(stage + r * AST + idx * 8);
                *(uint4*)(g_uv + (size_t)node * 256 + half * 128 + idx * 8) = val;
            }
        }
    }
}

// ---------------- edge phase v4: fp16 dot, u32 offsets ----------------
__global__ __launch_bounds__(256) void edge_eval(
    const void*  __restrict__ eidx,
    const float* __restrict__ b2,
    float* __restrict__ out,
    int E)
{
    const int lane = threadIdx.x & 31;
    const int hl   = lane & 15;       // feature group (8 features each)
    const int side = lane >> 4;       // which edge of each pair
    const int warp = blockIdx.x * 8 + (threadIdx.x >> 5);
    const long long e0 = (long long)warp * 8;
    if (e0 >= E) return;

    const uint4 w2p = ((const uint4*)g_w2h)[hl];     // 8 fp16 weights for this lane
    const __half2 w0 = bits_h2(w2p.x), w1 = bits_h2(w2p.y);
    const __half2 w2_ = bits_h2(w2p.z), w3 = bits_h2(w2p.w);
    const float  bias = b2[0];
    const int    is64 = g_idx_is64;
    const char* __restrict__ uvb = (const char*)g_uv;   // 512 B per node row

    int nr[4], nc[4];
    if (e0 + 8 <= E && (E & 1) == 0) {
        if (is64) {
            const longlong2* rp = (const longlong2*)eidx;
            #pragma unroll
            for (int t = 0; t < 4; ++t) {
                longlong2 rr = rp[(e0 >> 1) + t];
                nr[t] = (int)(side ? rr.y : rr.x);
                longlong2 cc = rp[(((long long)E + e0) >> 1) + t];
                nc[t] = (int)(side ? cc.y : cc.x);
            }
        } else {
            const int2* rp = (const int2*)eidx;
            #pragma unroll
            for (int t = 0; t < 4; ++t) {
                int2 rr = rp[(e0 >> 1) + t];
                nr[t] = side ? rr.y : rr.x;
                int2 cc = rp[(((long long)E + e0) >> 1) + t];
                nc[t] = side ? cc.y : cc.x;
            }
        }
    } else {
        #pragma unroll
        for (int t = 0; t < 4; ++t) {
            long long e = e0 + 2 * t + side;
            if (e >= E) e = e0;
            if (is64) {
                nr[t] = (int)((const long long*)eidx)[e];
                nc[t] = (int)((const long long*)eidx)[(long long)E + e];
            } else {
                nr[t] = ((const int*)eidx)[e];
                nc[t] = ((const int*)eidx)[(long long)E + e];
            }
        }
    }

    uint4 u[4], v[4];
    const unsigned hloff = (unsigned)hl * 16u;
    #pragma unroll
    for (int t = 0; t < 4; ++t) {
        u[t] = *(const uint4*)(uvb + ((unsigned)nr[t] * 512u + hloff));
        v[t] = *(const uint4*)(uvb + ((unsigned)nc[t] * 512u + 256u + hloff));
    }

    const __half2 z2 = __float2half2_rn(0.f);
    float s[4];
    #pragma unroll
    for (int t = 0; t < 4; ++t) {
        __half2 p0 = __hmax2(__hadd2(bits_h2(u[t].x), bits_h2(v[t].x)), z2);
        __half2 p1 = __hmax2(__hadd2(bits_h2(u[t].y), bits_h2(v[t].y)), z2);
        __half2 p2 = __hmax2(__hadd2(bits_h2(u[t].z), bits_h2(v[t].z)), z2);
        __half2 p3 = __hmax2(__hadd2(bits_h2(u[t].w), bits_h2(v[t].w)), z2);
        __half2 ah = __hmul2(p0, w0);
        ah = __hfma2(p1, w1, ah);
        ah = __hfma2(p2, w2_, ah);
        ah = __hfma2(p3, w3, ah);
        float2 f = __half22float2(ah);
        s[t] = f.x + f.y;
    }

    // value-splitting reduction over the 16 feature lanes (4 slots jointly)
    const unsigned FULLM = 0xffffffffu;
    const bool h8 = (hl & 8);
    float a0, a1;
    {
        float r0 = __shfl_xor_sync(FULLM, h8 ? s[0] : s[2], 8);
        a0 = (h8 ? s[2] : s[0]) + r0;
        float r1 = __shfl_xor_sync(FULLM, h8 ? s[1] : s[3], 8);
        a1 = (h8 ? s[3] : s[1]) + r1;
    }
    const bool h4 = (hl & 4);
    float b;
    {
        float r = __shfl_xor_sync(FULLM, h4 ? a0 : a1, 4);
        b = (h4 ? a1 : a0) + r;
    }
    b += __shfl_xor_sync(FULLM, b, 2);
    b += __shfl_xor_sync(FULLM, b, 1);

    int slot = ((hl >> 3) & 1) * 2 + ((hl >> 2) & 1);
    if ((hl & 3) == 0) {
        long long e = e0 + 2 * slot + side;
        if (e < E) out[e] = b + bias;
    }
}

extern "C" void kernel_launch(void* const* d_in, const int* in_sizes, int n_in,
                              void* d_out, int out_size)
{
    const float* x   = (const float*)d_in[0];
    const void*  ei  = d_in[1];
    const float* W1  = (const float*)d_in[2];
    const float* b1  = (const float*)d_in[3];
    const float* W2  = (const float*)d_in[4];
    const float* b2  = (const float*)d_in[5];
    float* out = (float*)d_out;

    int n_nodes = in_sizes[0] / 128;
    int E = in_sizes[1] / 2;

    long long total4 = (long long)n_nodes * 32;
    int cblocks = (int)((total4 + 255) / 256);
    convert_fp16<<<cblocks, 256>>>(x, W1, W2, ei, n_nodes);

    dim3 pgrid((n_nodes + 127) / 128, 2);
    precompute_uv<<<pgrid, NT>>>(b1, n_nodes);

    long long warps = ((long long)E + 7) / 8;
    int blocks = (int)((warps + 7) / 8);
    edge_eval<<<blocks, 256>>>(ei, b2, out, E);
}

// round 12
// speedup vs baseline: 20.1845x; 1.0014x over previous
#include <cuda_runtime.h>
#include <cuda_fp16.h>

// LinearEdgeDecoder, factored + fp16 table + HMMA precompute.
// R12: precompute register-prefetches chunk 1's tiles during chunk 0's mma
// (hides one exposed global-latency phase; launch_bounds(256,2) keeps 2 CTA/SM);
// convert_fp16 does 2 float4/thread for MLP.

#define ASK  72             // A chunk stride in halves (144B rows)
#define BSK  136            // B chunk stride in halves (272B rows)
#define AST  136            // staging stride in halves
#define NT   256

__device__ int    g_idx_is64;
__device__ __half g_uv[(size_t)131072 * 256];   // node table u|v (64 MB)
__device__ __half g_xh[(size_t)131072 * 128];   // x in fp16 (32 MB)
__device__ __half g_wh[256 * 128];              // W1 in fp16
__device__ __half g_w2h[128];                   // W2 in fp16

__device__ __forceinline__ unsigned h2_bits(__half2 h) {
    return *reinterpret_cast<unsigned*>(&h);
}
__device__ __forceinline__ __half2 bits_h2(unsigned b) {
    return *reinterpret_cast<__half2*>(&b);
}

__device__ __forceinline__ void ldsm_x4(unsigned& r0, unsigned& r1, unsigned& r2, unsigned& r3,
                                        unsigned addr) {
    asm volatile("ldmatrix.sync.aligned.m8n8.x4.shared.b16 {%0,%1,%2,%3}, [%4];"
                 : "=r"(r0), "=r"(r1), "=r"(r2), "=r"(r3) : "r"(addr));
}
__device__ __forceinline__ void ldsm_x4_t(unsigned& r0, unsigned& r1, unsigned& r2, unsigned& r3,
                                          unsigned addr) {
    asm volatile("ldmatrix.sync.aligned.m8n8.x4.trans.shared.b16 {%0,%1,%2,%3}, [%4];"
                 : "=r"(r0), "=r"(r1), "=r"(r2), "=r"(r3) : "r"(addr));
}
__device__ __forceinline__ void mma16816(float* c, const unsigned* a, unsigned b0, unsigned b1) {
    asm volatile(
        "mma.sync.aligned.m16n8k16.row.col.f32.f16.f16.f32 "
        "{%0,%1,%2,%3},{%4,%5,%6,%7},{%8,%9},{%0,%1,%2,%3};"
        : "+f"(c[0]), "+f"(c[1]), "+f"(c[2]), "+f"(c[3])
        : "r"(a[0]), "r"(a[1]), "r"(a[2]), "r"(a[3]), "r"(b0), "r"(b1));
}

// ---------------- one-shot fp16 conversion (+ dtype sniff) ----------------
// each thread converts 2 consecutive float4 (MLP=2)
__global__ __launch_bounds__(256) void convert_fp16(
    const float* __restrict__ x,    // [n_nodes, 128]
    const float* __restrict__ W1,   // [256, 128]
    const float* __restrict__ W2,   // [128]
    const void*  __restrict__ eidx,
    int n_nodes)
{
    long long i0 = ((long long)blockIdx.x * 256 + threadIdx.x) * 2;

    if (blockIdx.x == 0 && threadIdx.x < 32) {
        const long long* p = (const long long*)eidx;
        int bad = 0;
        #pragma unroll
        for (int t = 0; t < 2; ++t) {
            long long vv = p[threadIdx.x * 2 + t];
            if (vv < 0 || vv >= (long long)n_nodes) bad = 1;
        }
        unsigned m = __ballot_sync(0xffffffffu, bad);
        if (threadIdx.x == 0) g_idx_is64 = (m == 0u);
    }

    long long total = (long long)n_nodes * 32;   // float4 count of x
    if (i0 + 1 < total) {
        float4 f0 = ((const float4*)x)[i0];
        float4 f1 = ((const float4*)x)[i0 + 1];
        uint4 pk;
        pk.x = h2_bits(__floats2half2_rn(f0.x, f0.y));
        pk.y = h2_bits(__floats2half2_rn(f0.z, f0.w));
        pk.z = h2_bits(__floats2half2_rn(f1.x, f1.y));
        pk.w = h2_bits(__floats2half2_rn(f1.z, f1.w));
        *(uint4*)((uint2*)g_xh + i0) = pk;
    } else if (i0 < total) {
        float4 f0 = ((const float4*)x)[i0];
        uint2 pk;
        pk.x = h2_bits(__floats2half2_rn(f0.x, f0.y));
        pk.y = h2_bits(__floats2half2_rn(f0.z, f0.w));
        ((uint2*)g_xh)[i0] = pk;
    }
    if (i0 < 8192) {                             // W1 = 8192 float4
        #pragma unroll
        for (int t = 0; t < 2; ++t) {
            float4 f = ((const float4*)W1)[i0 + t];
            uint2 pk;
            pk.x = h2_bits(__floats2half2_rn(f.x, f.y));
            pk.y = h2_bits(__floats2half2_rn(f.z, f.w));
            ((uint2*)g_wh)[i0 + t] = pk;
        }
    }
    if (i0 < 32) {                               // W2 = 32 float4
        #pragma unroll
        for (int t = 0; t < 2; ++t) {
            float4 f = ((const float4*)W2)[i0 + t];
            uint2 pk;
            pk.x = h2_bits(__floats2half2_rn(f.x, f.y));
            pk.y = h2_bits(__floats2half2_rn(f.z, f.w));
            ((uint2*)g_w2h)[i0 + t] = pk;
        }
    }
}

// ---------------- node-table GEMM on tensor cores ----------------
// grid = (ceil(n_nodes/128), 2). CTA tile 128 nodes x 128 features, K=128 in 2
// chunks; chunk 1's global loads are register-prefetched during chunk 0's mma.
__global__ __launch_bounds__(NT, 2) void precompute_uv(
    const float* __restrict__ b1,   // [128]
    int n_nodes)
{
    __shared__ __align__(16) __half smem_s[128 * ASK + 64 * BSK];
    __half* sA = smem_s;
    __half* sB = smem_s + 128 * ASK;

    const int tid  = threadIdx.x;
    const int base = blockIdx.x * 128;
    const int half = blockIdx.y;     // 0 -> u (+b1), 1 -> v

    const int rA  = tid >> 1;
    const int sA_ = tid & 1;
    int nodeA = base + rA; if (nodeA >= n_nodes) nodeA = 0;

    const int rB  = tid >> 2;
    const int sB_ = tid & 3;

    const int w    = tid >> 5;
    const int lane = tid & 31;
    const int mw   = (w & 1) * 64;
    const int nw   = (w >> 1) * 32;
    const int lr   = lane & 15;
    const int lc   = (lane >> 4) * 8;

    float acc[4][4][4];
    #pragma unroll
    for (int i = 0; i < 4; ++i)
        #pragma unroll
        for (int j = 0; j < 4; ++j)
            #pragma unroll
            for (int t = 0; t < 4; ++t) acc[i][j][t] = 0.f;

    const unsigned sA0 = (unsigned)__cvta_generic_to_shared(sA);
    const unsigned sB0 = (unsigned)__cvta_generic_to_shared(sB);
    const uint4* __restrict__ xh4 = (const uint4*)g_xh;   // 16 per node row
    const uint4* __restrict__ wh4 = (const uint4*)g_wh;   // 16 per W1 row

    // ---- chunk 0 tiles -> smem ----
    #pragma unroll
    for (int q = 0; q < 4; ++q) {
        uint4 val = xh4[(size_t)nodeA * 16 + sA_ * 4 + q];
        *(uint4*)(sA + rA * ASK + sA_ * 32 + q * 8) = val;
    }
    #pragma unroll
    for (int q = 0; q < 4; ++q) {
        uint4 val = wh4[(size_t)(half * 128 + rB) * 16 + sB_ * 4 + q];
        *(uint4*)(sB + rB * BSK + sB_ * 32 + q * 8) = val;
    }
    __syncthreads();

    // ---- prefetch chunk 1 into registers (completes under chunk-0 mma) ----
    uint4 pa[4], pb[4];
    #pragma unroll
    for (int q = 0; q < 4; ++q)
        pa[q] = xh4[(size_t)nodeA * 16 + 8 + sA_ * 4 + q];
    #pragma unroll
    for (int q = 0; q < 4; ++q)
        pb[q] = wh4[(size_t)(half * 128 + 64 + rB) * 16 + sB_ * 4 + q];

    // ---- chunk 0 mma ----
    #pragma unroll
    for (int ks = 0; ks < 4; ++ks) {
        const int k0 = ks * 16;
        unsigned a[4][4];
        #pragma unroll
        for (int mt = 0; mt < 4; ++mt) {
            unsigned addr = sA0 + ((mw + mt * 16 + lr) * ASK + k0 + lc) * 2;
            ldsm_x4(a[mt][0], a[mt][1], a[mt][2], a[mt][3], addr);
        }
        unsigned b[4][2];
        #pragma unroll
        for (int pr = 0; pr < 2; ++pr) {
            unsigned addr = sB0 + ((k0 + lr) * BSK + nw + pr * 16 + lc) * 2;
            unsigned r0, r1, r2, r3;
            ldsm_x4_t(r0, r1, r2, r3, addr);
            b[pr * 2][0] = r0;     b[pr * 2][1] = r1;
            b[pr * 2 + 1][0] = r2; b[pr * 2 + 1][1] = r3;
        }
        #pragma unroll
        for (int mt = 0; mt < 4; ++mt)
            #pragma unroll
            for (int nt = 0; nt < 4; ++nt)
                mma16816(acc[mt][nt], a[mt], b[nt][0], b[nt][1]);
    }
    __syncthreads();

    // ---- store chunk 1 tiles from registers ----
    #pragma unroll
    for (int q = 0; q < 4; ++q)
        *(uint4*)(sA + rA * ASK + sA_ * 32 + q * 8) = pa[q];
    #pragma unroll
    for (int q = 0; q < 4; ++q)
        *(uint4*)(sB + rB * BSK + sB_ * 32 + q * 8) = pb[q];
    __syncthreads();

    // ---- chunk 1 mma ----
    #pragma unroll
    for (int ks = 0; ks < 4; ++ks) {
        const int k0 = ks * 16;
        unsigned a[4][4];
        #pragma unroll
        for (int mt = 0; mt < 4; ++mt) {
            unsigned addr = sA0 + ((mw + mt * 16 + lr) * ASK + k0 + lc) * 2;
            ldsm_x4(a[mt][0], a[mt][1], a[mt][2], a[mt][3], addr);
        }
        unsigned b[4][2];
        #pragma unroll
        for (int pr = 0; pr < 2; ++pr) {
            unsigned addr = sB0 + ((k0 + lr) * BSK + nw + pr * 16 + lc) * 2;
            unsigned r0, r1, r2, r3;
            ldsm_x4_t(r0, r1, r2, r3, addr);
            b[pr * 2][0] = r0;     b[pr * 2][1] = r1;
            b[pr * 2 + 1][0] = r2; b[pr * 2 + 1][1] = r3;
        }
        #pragma unroll
        for (int mt = 0; mt < 4; ++mt)
            #pragma unroll
            for (int nt = 0; nt < 4; ++nt)
                mma16816(acc[mt][nt], a[mt], b[nt][0], b[nt][1]);
    }
    __syncthreads();

    // ---- epilogue: +b1 (u half), fp16, stage through smem, coalesced copy ----
    const int g  = lane >> 2;
    const int t2 = (lane & 3) * 2;
    float bx[4], by[4];
    #pragma unroll
    for (int nt = 0; nt < 4; ++nt) {
        int c0 = nw + nt * 8 + t2;
        bx[nt] = (half == 0) ? b1[c0]     : 0.f;
        by[nt] = (half == 0) ? b1[c0 + 1] : 0.f;
    }

    __half* stage = smem_s;
    #pragma unroll
    for (int mt = 0; mt < 4; ++mt) {
        #pragma unroll
        for (int nt = 0; nt < 4; ++nt) {
            int row = mw + mt * 16 + g;
            int col = nw + nt * 8 + t2;
            *(__half2*)(stage + row * AST + col) =
                __floats2half2_rn(acc[mt][nt][0] + bx[nt], acc[mt][nt][1] + by[nt]);
            *(__half2*)(stage + (row + 8) * AST + col) =
                __floats2half2_rn(acc[mt][nt][2] + bx[nt], acc[mt][nt][3] + by[nt]);
        }
    }
    __syncthreads();

    #pragma unroll
    for (int rr = 0; rr < 4; ++rr) {
        int r = w * 16 + rr * 4 + (lane >> 3);
        int node = base + r;
        if (node < n_nodes) {
            #pragma unroll
            for (int it = 0; it < 2; ++it) {
                int idx = (lane & 7) + it * 8;
                uint4 val = *(uint4*)(stage + r * AST + idx * 8);
                *(uint4*)(g_uv + (size_t)node * 256 + half * 128 + idx * 8) = val;
            }
        }
    }
}

// ---------------- edge phase v4: fp16 dot, u32 offsets (unchanged) ----------------
__global__ __launch_bounds__(256) void edge_eval(
    const void*  __restrict__ eidx,
    const float* __restrict__ b2,
    float* __restrict__ out,
    int E)
{
    const int lane = threadIdx.x & 31;
    const int hl   = lane & 15;       // feature group (8 features each)
    const int side = lane >> 4;       // which edge of each pair
    const int warp = blockIdx.x * 8 + (threadIdx.x >> 5);
    const long long e0 = (long long)warp * 8;
    if (e0 >= E) return;

    const uint4 w2p = ((const uint4*)g_w2h)[hl];     // 8 fp16 weights for this lane
    const __half2 w0 = bits_h2(w2p.x), w1 = bits_h2(w2p.y);
    const __half2 w2_ = bits_h2(w2p.z), w3 = bits_h2(w2p.w);
    const float  bias = b2[0];
    const int    is64 = g_idx_is64;
    const char* __restrict__ uvb = (const char*)g_uv;   // 512 B per node row

    int nr[4], nc[4];
    if (e0 + 8 <= E && (E & 1) == 0) {
        if (is64) {
            const longlong2* rp = (const longlong2*)eidx;
            #pragma unroll
            for (int t = 0; t < 4; ++t) {
                longlong2 rr = rp[(e0 >> 1) + t];
                nr[t] = (int)(side ? rr.y : rr.x);
                longlong2 cc = rp[(((long long)E + e0) >> 1) + t];
                nc[t] = (int)(side ? cc.y : cc.x);
            }
        } else {
            const int2* rp = (const int2*)eidx;
            #pragma unroll
            for (int t = 0; t < 4; ++t) {
                int2 rr = rp[(e0 >> 1) + t];
                nr[t] = side ? rr.y : rr.x;
                int2 cc = rp[(((long long)E + e0) >> 1) + t];
                nc[t] = side ? cc.y : cc.x;
            }
        }
    } else {
        #pragma unroll
        for (int t = 0; t < 4; ++t) {
            long long e = e0 + 2 * t + side;
            if (e >= E) e = e0;
            if (is64) {
                nr[t] = (int)((const long long*)eidx)[e];
                nc[t] = (int)((const long long*)eidx)[(long long)E + e];
            } else {
                nr[t] = ((const int*)eidx)[e];
                nc[t] = ((const int*)eidx)[(long long)E + e];
            }
        }
    }

    uint4 u[4], v[4];
    const unsigned hloff = (unsigned)hl * 16u;
    #pragma unroll
    for (int t = 0; t < 4; ++t) {
        u[t] = *(const uint4*)(uvb + ((unsigned)nr[t] * 512u + hloff));
        v[t] = *(const uint4*)(uvb + ((unsigned)nc[t] * 512u + 256u + hloff));
    }

    const __half2 z2 = __float2half2_rn(0.f);
    float s[4];
    #pragma unroll
    for (int t = 0; t < 4; ++t) {
        __half2 p0 = __hmax2(__hadd2(bits_h2(u[t].x), bits_h2(v[t].x)), z2);
        __half2 p1 = __hmax2(__hadd2(bits_h2(u[t].y), bits_h2(v[t].y)), z2);
        __half2 p2 = __hmax2(__hadd2(bits_h2(u[t].z), bits_h2(v[t].z)), z2);
        __half2 p3 = __hmax2(__hadd2(bits_h2(u[t].w), bits_h2(v[t].w)), z2);
        __half2 ah = __hmul2(p0, w0);
        ah = __hfma2(p1, w1, ah);
        ah = __hfma2(p2, w2_, ah);
        ah = __hfma2(p3, w3, ah);
        float2 f = __half22float2(ah);
        s[t] = f.x + f.y;
    }

    const unsigned FULLM = 0xffffffffu;
    const bool h8 = (hl & 8);
    float a0, a1;
    {
        float r0 = __shfl_xor_sync(FULLM, h8 ? s[0] : s[2], 8);
        a0 = (h8 ? s[2] : s[0]) + r0;
        float r1 = __shfl_xor_sync(FULLM, h8 ? s[1] : s[3], 8);
        a1 = (h8 ? s[3] : s[1]) + r1;
    }
    const bool h4 = (hl & 4);
    float b;
    {
        float r = __shfl_xor_sync(FULLM, h4 ? a0 : a1, 4);
        b = (h4 ? a1 : a0) + r;
    }
    b += __shfl_xor_sync(FULLM, b, 2);
    b += __shfl_xor_sync(FULLM, b, 1);

    int slot = ((hl >> 3) & 1) * 2 + ((hl >> 2) & 1);
    if ((hl & 3) == 0) {
        long long e = e0 + 2 * slot + side;
        if (e < E) out[e] = b + bias;
    }
}

extern "C" void kernel_launch(void* const* d_in, const int* in_sizes, int n_in,
                              void* d_out, int out_size)
{
    const float* x   = (const float*)d_in[0];
    const void*  ei  = d_in[1];
    const float* W1  = (const float*)d_in[2];
    const float* b1  = (const float*)d_in[3];
    const float* W2  = (const float*)d_in[4];
    const float* b2  = (const float*)d_in[5];
    float* out = (float*)d_out;

    int n_nodes = in_sizes[0] / 128;
    int E = in_sizes[1] / 2;

    long long total4 = (long long)n_nodes * 32;
    int cblocks = (int)((total4 / 2 + 255) / 256);
    convert_fp16<<<cblocks, 256>>>(x, W1, W2, ei, n_nodes);

    dim3 pgrid((n_nodes + 127) / 128, 2);
    precompute_uv<<<pgrid, NT>>>(b1, n_nodes);

    long long warps = ((long long)E + 7) / 8;
    int blocks = (int)((warps + 7) / 8);
    edge_eval<<<blocks, 256>>>(ei, b2, out, E);
}

// round 13
// speedup vs baseline: 21.8099x; 1.0805x over previous
#include <cuda_runtime.h>
#include <cuda_fp16.h>

// LinearEdgeDecoder, factored + fp16 table + HMMA precompute.
// R13: precompute pipelined with cp.async double-buffering (K=128 as 4 chunks
// of 32; loads for chunk c+1 run under chunk c's mma; zero register cost --
// R12's register prefetch spilled under launch_bounds(256,2) and regressed).

#define ASK2 40             // A chunk stride in halves (80B rows, ldmatrix conflict-free)
#define BSK  136            // B chunk stride in halves (272B rows)
#define AST  136            // staging stride in halves
#define NT   256
// per-stage sizes in halves
#define ABUF (128 * ASK2)   // 5120
#define BBUF (32 * BSK)     // 4352
#define STAGE_H (ABUF + BBUF)  // 9472

__device__ int    g_idx_is64;
__device__ __align__(16) __half g_uv[(size_t)131072 * 256];   // node table u|v (64 MB)
__device__ __align__(16) __half g_xh[(size_t)131072 * 128];   // x in fp16 (32 MB)
__device__ __align__(16) __half g_wh[256 * 128];              // W1 in fp16
__device__ __align__(16) __half g_w2h[128];                   // W2 in fp16

__device__ __forceinline__ unsigned h2_bits(__half2 h) {
    return *reinterpret_cast<unsigned*>(&h);
}
__device__ __forceinline__ __half2 bits_h2(unsigned b) {
    return *reinterpret_cast<__half2*>(&b);
}

__device__ __forceinline__ void cp16(unsigned dst, const void* src) {
    asm volatile("cp.async.cg.shared.global [%0], [%1], 16;" :: "r"(dst), "l"(src));
}
__device__ __forceinline__ void cp_commit() {
    asm volatile("cp.async.commit_group;");
}
__device__ __forceinline__ void cp_wait_all() {
    asm volatile("cp.async.wait_group 0;");
}

__device__ __forceinline__ void ldsm_x4(unsigned& r0, unsigned& r1, unsigned& r2, unsigned& r3,
                                        unsigned addr) {
    asm volatile("ldmatrix.sync.aligned.m8n8.x4.shared.b16 {%0,%1,%2,%3}, [%4];"
                 : "=r"(r0), "=r"(r1), "=r"(r2), "=r"(r3) : "r"(addr));
}
__device__ __forceinline__ void ldsm_x4_t(unsigned& r0, unsigned& r1, unsigned& r2, unsigned& r3,
                                          unsigned addr) {
    asm volatile("ldmatrix.sync.aligned.m8n8.x4.trans.shared.b16 {%0,%1,%2,%3}, [%4];"
                 : "=r"(r0), "=r"(r1), "=r"(r2), "=r"(r3) : "r"(addr));
}
__device__ __forceinline__ void mma16816(float* c, const unsigned* a, unsigned b0, unsigned b1) {
    asm volatile(
        "mma.sync.aligned.m16n8k16.row.col.f32.f16.f16.f32 "
        "{%0,%1,%2,%3},{%4,%5,%6,%7},{%8,%9},{%0,%1,%2,%3};"
        : "+f"(c[0]), "+f"(c[1]), "+f"(c[2]), "+f"(c[3])
        : "r"(a[0]), "r"(a[1]), "r"(a[2]), "r"(a[3]), "r"(b0), "r"(b1));
}

// ---------------- one-shot fp16 conversion (+ dtype sniff) ----------------
__global__ __launch_bounds__(256) void convert_fp16(
    const float* __restrict__ x,    // [n_nodes, 128]
    const float* __restrict__ W1,   // [256, 128]
    const float* __restrict__ W2,   // [128]
    const void*  __restrict__ eidx,
    int n_nodes)
{
    long long i0 = ((long long)blockIdx.x * 256 + threadIdx.x) * 2;

    if (blockIdx.x == 0 && threadIdx.x < 32) {
        const long long* p = (const long long*)eidx;
        int bad = 0;
        #pragma unroll
        for (int t = 0; t < 2; ++t) {
            long long vv = p[threadIdx.x * 2 + t];
            if (vv < 0 || vv >= (long long)n_nodes) bad = 1;
        }
        unsigned m = __ballot_sync(0xffffffffu, bad);
        if (threadIdx.x == 0) g_idx_is64 = (m == 0u);
    }

    long long total = (long long)n_nodes * 32;   // float4 count of x
    if (i0 + 1 < total) {
        float4 f0 = ((const float4*)x)[i0];
        float4 f1 = ((const float4*)x)[i0 + 1];
        uint4 pk;
        pk.x = h2_bits(__floats2half2_rn(f0.x, f0.y));
        pk.y = h2_bits(__floats2half2_rn(f0.z, f0.w));
        pk.z = h2_bits(__floats2half2_rn(f1.x, f1.y));
        pk.w = h2_bits(__floats2half2_rn(f1.z, f1.w));
        *(uint4*)((uint2*)g_xh + i0) = pk;
    } else if (i0 < total) {
        float4 f0 = ((const float4*)x)[i0];
        uint2 pk;
        pk.x = h2_bits(__floats2half2_rn(f0.x, f0.y));
        pk.y = h2_bits(__floats2half2_rn(f0.z, f0.w));
        ((uint2*)g_xh)[i0] = pk;
    }
    if (i0 < 8192) {                             // W1 = 8192 float4
        #pragma unroll
        for (int t = 0; t < 2; ++t) {
            float4 f = ((const float4*)W1)[i0 + t];
            uint2 pk;
            pk.x = h2_bits(__floats2half2_rn(f.x, f.y));
            pk.y = h2_bits(__floats2half2_rn(f.z, f.w));
            ((uint2*)g_wh)[i0 + t] = pk;
        }
    }
    if (i0 < 32) {                               // W2 = 32 float4
        #pragma unroll
        for (int t = 0; t < 2; ++t) {
            float4 f = ((const float4*)W2)[i0 + t];
            uint2 pk;
            pk.x = h2_bits(__floats2half2_rn(f.x, f.y));
            pk.y = h2_bits(__floats2half2_rn(f.z, f.w));
            ((uint2*)g_w2h)[i0 + t] = pk;
        }
    }
}

// ---------------- node-table GEMM on tensor cores, cp.async pipelined ----------------
// grid = (ceil(n_nodes/128), 2). CTA tile 128 nodes x 128 features,
// K=128 as 4 chunks of 32, double-buffered.
__global__ __launch_bounds__(NT) void precompute_uv(
    const float* __restrict__ b1,   // [128]
    int n_nodes)
{
    __shared__ __align__(16) __half smem_s[2 * STAGE_H];   // 37888 B

    const int tid  = threadIdx.x;
    const int base = blockIdx.x * 128;
    const int half = blockIdx.y;     // 0 -> u (+b1), 1 -> v

    // loader coords
    const int rA   = tid >> 1;       // node row 0..127
    const int segA = tid & 1;        // 16-half segment within 32-half chunk row
    int nodeA = base + rA; if (nodeA >= n_nodes) nodeA = 0;
    const int rowB  = tid >> 3;      // k row 0..31
    const int laneB = tid & 7;       // 16-half segment within 128-half row

    // warp/mma coords
    const int w    = tid >> 5;
    const int lane = tid & 31;
    const int mw   = (w & 1) * 64;
    const int nw   = (w >> 1) * 32;
    const int lr   = lane & 15;
    const int lc   = (lane >> 4) * 8;

    float acc[4][4][4];
    #pragma unroll
    for (int i = 0; i < 4; ++i)
        #pragma unroll
        for (int j = 0; j < 4; ++j)
            #pragma unroll
            for (int t = 0; t < 4; ++t) acc[i][j][t] = 0.f;

    const unsigned sbase = (unsigned)__cvta_generic_to_shared(smem_s);

    // per-thread fixed parts of cp.async addressing
    const __half* srcA_base = g_xh + (size_t)nodeA * 128 + segA * 16;
    const __half* srcB_base = g_wh + (size_t)(half * 128 + rowB) * 128 + laneB * 16;
    const unsigned dstA_off = (unsigned)(rA * ASK2 + segA * 16) * 2;
    const unsigned dstB_off = (unsigned)(ABUF + rowB * BSK + laneB * 16) * 2;

    // issue chunk c's loads into stage s
    auto load_chunk = [&](int c, int s) {
        unsigned sb = sbase + (unsigned)(s * STAGE_H) * 2;
        unsigned dA = sb + dstA_off;
        const __half* pA = srcA_base + c * 32;
        cp16(dA, pA);
        cp16(dA + 16, pA + 8);
        unsigned dB = sb + dstB_off;
        const __half* pB = srcB_base + (size_t)c * 32 * 128;
        cp16(dB, pB);
        cp16(dB + 16, pB + 8);
        cp_commit();
    };

    load_chunk(0, 0);

    #pragma unroll
    for (int c = 0; c < 4; ++c) {
        const int s = c & 1;
        cp_wait_all();          // chunk c resident (chunk c+1 not yet committed)
        __syncthreads();        // publish; also: all warps done reading stage s (chunk c-2)

        if (c < 3) load_chunk(c + 1, s ^ 1);

        const unsigned sA0 = sbase + (unsigned)(s * STAGE_H) * 2;
        const unsigned sB0 = sA0 + (unsigned)ABUF * 2;

        #pragma unroll
        for (int ks = 0; ks < 2; ++ks) {
            const int k0 = ks * 16;
            unsigned a[4][4];
            #pragma unroll
            for (int mt = 0; mt < 4; ++mt) {
                unsigned addr = sA0 + ((mw + mt * 16 + lr) * ASK2 + k0 + lc) * 2;
                ldsm_x4(a[mt][0], a[mt][1], a[mt][2], a[mt][3], addr);
            }
            unsigned b[4][2];
            #pragma unroll
            for (int pr = 0; pr < 2; ++pr) {
                unsigned addr = sB0 + ((k0 + lr) * BSK + nw + pr * 16 + lc) * 2;
                unsigned r0, r1, r2, r3;
                ldsm_x4_t(r0, r1, r2, r3, addr);
                b[pr * 2][0] = r0;     b[pr * 2][1] = r1;
                b[pr * 2 + 1][0] = r2; b[pr * 2 + 1][1] = r3;
            }
            #pragma unroll
            for (int mt = 0; mt < 4; ++mt)
                #pragma unroll
                for (int nt = 0; nt < 4; ++nt)
                    mma16816(acc[mt][nt], a[mt], b[nt][0], b[nt][1]);
        }
    }
    __syncthreads();    // all mma reads done before staging overwrites buffers

    // ---- epilogue: +b1 (u half), fp16, stage through smem, coalesced copy ----
    const int g  = lane >> 2;
    const int t2 = (lane & 3) * 2;
    float bx[4], by[4];
    #pragma unroll
    for (int nt = 0; nt < 4; ++nt) {
        int c0 = nw + nt * 8 + t2;
        bx[nt] = (half == 0) ? b1[c0]     : 0.f;
        by[nt] = (half == 0) ? b1[c0 + 1] : 0.f;
    }

    __half* stage = smem_s;   // 128 x AST(136) = 34816 halves? (17408 halves = 34816 B) fits
    #pragma unroll
    for (int mt = 0; mt < 4; ++mt) {
        #pragma unroll
        for (int nt = 0; nt < 4; ++nt) {
            int row = mw + mt * 16 + g;
            int col = nw + nt * 8 + t2;
            *(__half2*)(stage + row * AST + col) =
                __floats2half2_rn(acc[mt][nt][0] + bx[nt], acc[mt][nt][1] + by[nt]);
            *(__half2*)(stage + (row + 8) * AST + col) =
                __floats2half2_rn(acc[mt][nt][2] + bx[nt], acc[mt][nt][3] + by[nt]);
        }
    }
    __syncthreads();

    #pragma unroll
    for (int rr = 0; rr < 4; ++rr) {
        int r = w * 16 + rr * 4 + (lane >> 3);
        int node = base + r;
        if (node < n_nodes) {
            #pragma unroll
            for (int it = 0; it < 2; ++it) {
                int idx = (lane & 7) + it * 8;
                uint4 val = *(uint4*)(stage + r * AST + idx * 8);
                *(uint4*)(g_uv + (size_t)node * 256 + half * 128 + idx * 8) = val;
            }
        }
    }
}

// ---------------- edge phase v4: fp16 dot, u32 offsets (unchanged) ----------------
__global__ __launch_bounds__(256) void edge_eval(
    const void*  __restrict__ eidx,
    const float* __restrict__ b2,
    float* __restrict__ out,
    int E)
{
    const int lane = threadIdx.x & 31;
    const int hl   = lane & 15;       // feature group (8 features each)
    const int side = lane >> 4;       // which edge of each pair
    const int warp = blockIdx.x * 8 + (threadIdx.x >> 5);
    const long long e0 = (long long)warp * 8;
    if (e0 >= E) return;

    const uint4 w2p = ((const uint4*)g_w2h)[hl];     // 8 fp16 weights for this lane
    const __half2 w0 = bits_h2(w2p.x), w1 = bits_h2(w2p.y);
    const __half2 w2_ = bits_h2(w2p.z), w3 = bits_h2(w2p.w);
    const float  bias = b2[0];
    const int    is64 = g_idx_is64;
    const char* __restrict__ uvb = (const char*)g_uv;   // 512 B per node row

    int nr[4], nc[4];
    if (e0 + 8 <= E && (E & 1) == 0) {
        if (is64) {
            const longlong2* rp = (const longlong2*)eidx;
            #pragma unroll
            for (int t = 0; t < 4; ++t) {
                longlong2 rr = rp[(e0 >> 1) + t];
                nr[t] = (int)(side ? rr.y : rr.x);
                longlong2 cc = rp[(((long long)E + e0) >> 1) + t];
                nc[t] = (int)(side ? cc.y : cc.x);
            }
        } else {
            const int2* rp = (const int2*)eidx;
            #pragma unroll
            for (int t = 0; t < 4; ++t) {
                int2 rr = rp[(e0 >> 1) + t];
                nr[t] = side ? rr.y : rr.x;
                int2 cc = rp[(((long long)E + e0) >> 1) + t];
                nc[t] = side ? cc.y : cc.x;
            }
        }
    } else {
        #pragma unroll
        for (int t = 0; t < 4; ++t) {
            long long e = e0 + 2 * t + side;
            if (e >= E) e = e0;
            if (is64) {
                nr[t] = (int)((const long long*)eidx)[e];
                nc[t] = (int)((const long long*)eidx)[(long long)E + e];
            } else {
                nr[t] = ((const int*)eidx)[e];
                nc[t] = ((const int*)eidx)[(long long)E + e];
            }
        }
    }

    uint4 u[4], v[4];
    const unsigned hloff = (unsigned)hl * 16u;
    #pragma unroll
    for (int t = 0; t < 4; ++t) {
        u[t] = *(const uint4*)(uvb + ((unsigned)nr[t] * 512u + hloff));
        v[t] = *(const uint4*)(uvb + ((unsigned)nc[t] * 512u + 256u + hloff));
    }

    const __half2 z2 = __float2half2_rn(0.f);
    float s[4];
    #pragma unroll
    for (int t = 0; t < 4; ++t) {
        __half2 p0 = __hmax2(__hadd2(bits_h2(u[t].x), bits_h2(v[t].x)), z2);
        __half2 p1 = __hmax2(__hadd2(bits_h2(u[t].y), bits_h2(v[t].y)), z2);
        __half2 p2 = __hmax2(__hadd2(bits_h2(u[t].z), bits_h2(v[t].z)), z2);
        __half2 p3 = __hmax2(__hadd2(bits_h2(u[t].w), bits_h2(v[t].w)), z2);
        __half2 ah = __hmul2(p0, w0);
        ah = __hfma2(p1, w1, ah);
        ah = __hfma2(p2, w2_, ah);
        ah = __hfma2(p3, w3, ah);
        float2 f = __half22float2(ah);
        s[t] = f.x + f.y;
    }

    const unsigned FULLM = 0xffffffffu;
    const bool h8 = (hl & 8);
    float a0, a1;
    {
        float r0 = __shfl_xor_sync(FULLM, h8 ? s[0] : s[2], 8);
        a0 = (h8 ? s[2] : s[0]) + r0;
        float r1 = __shfl_xor_sync(FULLM, h8 ? s[1] : s[3], 8);
        a1 = (h8 ? s[3] : s[1]) + r1;
    }
    const bool h4 = (hl & 4);
    float b;
    {
        float r = __shfl_xor_sync(FULLM, h4 ? a0 : a1, 4);
        b = (h4 ? a1 : a0) + r;
    }
    b += __shfl_xor_sync(FULLM, b, 2);
    b += __shfl_xor_sync(FULLM, b, 1);

    int slot = ((hl >> 3) & 1) * 2 + ((hl >> 2) & 1);
    if ((hl & 3) == 0) {
        long long e = e0 + 2 * slot + side;
        if (e < E) out[e] = b + bias;
    }
}

extern "C" void kernel_launch(void* const* d_in, const int* in_sizes, int n_in,
                              void* d_out, int out_size)
{
    const float* x   = (const float*)d_in[0];
    const void*  ei  = d_in[1];
    const float* W1  = (const float*)d_in[2];
    const float* b1  = (const float*)d_in[3];
    const float* W2  = (const float*)d_in[4];
    const float* b2  = (const float*)d_in[5];
    float* out = (float*)d_out;

    int n_nodes = in_sizes[0] / 128;
    int E = in_sizes[1] / 2;

    long long total4 = (long long)n_nodes * 32;
    int cblocks = (int)((total4 / 2 + 255) / 256);
    convert_fp16<<<cblocks, 256>>>(x, W1, W2, ei, n_nodes);

    dim3 pgrid((n_nodes + 127) / 128, 2);
    precompute_uv<<<pgrid, NT>>>(b1, n_nodes);

    long long warps = ((long long)E + 7) / 8;
    int blocks = (int)((warps + 7) / 8);
    edge_eval<<<blocks, 256>>>(ei, b2, out, E);
}

// round 15
// speedup vs baseline: 21.8232x; 1.0006x over previous
#include <cuda_runtime.h>
#include <cuda_fp16.h>

// LinearEdgeDecoder, factored + fp16 table + HMMA precompute.
// R15 (= R14 resubmit; prior run died to container flake, no kernel signal):
// cp.async pipeline keeps TWO chunks in flight (R13 waited each chunk to
// completion before committing the next, leaving ~1 load-latency exposed).

#define ASK2 40             // A chunk stride in halves (80B rows, ldmatrix conflict-free)
#define BSK  136            // B chunk stride in halves (272B rows)
#define AST  136            // staging stride in halves
#define NT   256
#define ABUF (128 * ASK2)   // 5120 halves per A stage
#define BBUF (32 * BSK)     // 4352 halves per B stage
#define STAGE_H (ABUF + BBUF)

__device__ int    g_idx_is64;
__device__ __align__(16) __half g_uv[(size_t)131072 * 256];   // node table u|v (64 MB)
__device__ __align__(16) __half g_xh[(size_t)131072 * 128];   // x in fp16 (32 MB)
__device__ __align__(16) __half g_wh[256 * 128];              // W1 in fp16
__device__ __align__(16) __half g_w2h[128];                   // W2 in fp16

__device__ __forceinline__ unsigned h2_bits(__half2 h) {
    return *reinterpret_cast<unsigned*>(&h);
}
__device__ __forceinline__ __half2 bits_h2(unsigned b) {
    return *reinterpret_cast<__half2*>(&b);
}

__device__ __forceinline__ void cp16(unsigned dst, const void* src) {
    asm volatile("cp.async.cg.shared.global [%0], [%1], 16;" :: "r"(dst), "l"(src));
}
__device__ __forceinline__ void cp_commit() {
    asm volatile("cp.async.commit_group;");
}
template <int N>
__device__ __forceinline__ void cp_wait() {
    asm volatile("cp.async.wait_group %0;" :: "n"(N));
}

__device__ __forceinline__ void ldsm_x4(unsigned& r0, unsigned& r1, unsigned& r2, unsigned& r3,
                                        unsigned addr) {
    asm volatile("ldmatrix.sync.aligned.m8n8.x4.shared.b16 {%0,%1,%2,%3}, [%4];"
                 : "=r"(r0), "=r"(r1), "=r"(r2), "=r"(r3) : "r"(addr));
}
__device__ __forceinline__ void ldsm_x4_t(unsigned& r0, unsigned& r1, unsigned& r2, unsigned& r3,
                                          unsigned addr) {
    asm volatile("ldmatrix.sync.aligned.m8n8.x4.trans.shared.b16 {%0,%1,%2,%3}, [%4];"
                 : "=r"(r0), "=r"(r1), "=r"(r2), "=r"(r3) : "r"(addr));
}
__device__ __forceinline__ void mma16816(float* c, const unsigned* a, unsigned b0, unsigned b1) {
    asm volatile(
        "mma.sync.aligned.m16n8k16.row.col.f32.f16.f16.f32 "
        "{%0,%1,%2,%3},{%4,%5,%6,%7},{%8,%9},{%0,%1,%2,%3};"
        : "+f"(c[0]), "+f"(c[1]), "+f"(c[2]), "+f"(c[3])
        : "r"(a[0]), "r"(a[1]), "r"(a[2]), "r"(a[3]), "r"(b0), "r"(b1));
}

// ---------------- one-shot fp16 conversion (+ dtype sniff) ----------------
__global__ __launch_bounds__(256) void convert_fp16(
    const float* __restrict__ x,    // [n_nodes, 128]
    const float* __restrict__ W1,   // [256, 128]
    const float* __restrict__ W2,   // [128]
    const void*  __restrict__ eidx,
    int n_nodes)
{
    long long i0 = ((long long)blockIdx.x * 256 + threadIdx.x) * 2;

    if (blockIdx.x == 0 && threadIdx.x < 32) {
        const long long* p = (const long long*)eidx;
        int bad = 0;
        #pragma unroll
        for (int t = 0; t < 2; ++t) {
            long long vv = p[threadIdx.x * 2 + t];
            if (vv < 0 || vv >= (long long)n_nodes) bad = 1;
        }
        unsigned m = __ballot_sync(0xffffffffu, bad);
        if (threadIdx.x == 0) g_idx_is64 = (m == 0u);
    }

    long long total = (long long)n_nodes * 32;   // float4 count of x
    if (i0 + 1 < total) {
        float4 f0 = ((const float4*)x)[i0];
        float4 f1 = ((const float4*)x)[i0 + 1];
        uint4 pk;
        pk.x = h2_bits(__floats2half2_rn(f0.x, f0.y));
        pk.y = h2_bits(__floats2half2_rn(f0.z, f0.w));
        pk.z = h2_bits(__floats2half2_rn(f1.x, f1.y));
        pk.w = h2_bits(__floats2half2_rn(f1.z, f1.w));
        *(uint4*)((uint2*)g_xh + i0) = pk;
    } else if (i0 < total) {
        float4 f0 = ((const float4*)x)[i0];
        uint2 pk;
        pk.x = h2_bits(__floats2half2_rn(f0.x, f0.y));
        pk.y = h2_bits(__floats2half2_rn(f0.z, f0.w));
        ((uint2*)g_xh)[i0] = pk;
    }
    if (i0 < 8192) {                             // W1 = 8192 float4
        #pragma unroll
        for (int t = 0; t < 2; ++t) {
            float4 f = ((const float4*)W1)[i0 + t];
            uint2 pk;
            pk.x = h2_bits(__floats2half2_rn(f.x, f.y));
            pk.y = h2_bits(__floats2half2_rn(f.z, f.w));
            ((uint2*)g_wh)[i0 + t] = pk;
        }
    }
    if (i0 < 32) {                               // W2 = 32 float4
        #pragma unroll
        for (int t = 0; t < 2; ++t) {
            float4 f = ((const float4*)W2)[i0 + t];
            uint2 pk;
            pk.x = h2_bits(__floats2half2_rn(f.x, f.y));
            pk.y = h2_bits(__floats2half2_rn(f.z, f.w));
            ((uint2*)g_w2h)[i0 + t] = pk;
        }
    }
}

// ---------------- node-table GEMM on tensor cores, 2-deep cp.async pipeline ----------------
// grid = (ceil(n_nodes/128), 2). CTA tile 128 nodes x 128 features,
// K=128 as 4 chunks of 32, double-buffered with 2 loads in flight.
__global__ __launch_bounds__(NT) void precompute_uv(
    const float* __restrict__ b1,   // [128]
    int n_nodes)
{
    __shared__ __align__(16) __half smem_s[2 * STAGE_H];   // 37888 B

    const int tid  = threadIdx.x;
    const int base = blockIdx.x * 128;
    const int half = blockIdx.y;     // 0 -> u (+b1), 1 -> v

    const int rA   = tid >> 1;       // node row 0..127
    const int segA = tid & 1;        // 16-half segment within 32-half chunk row
    int nodeA = base + rA; if (nodeA >= n_nodes) nodeA = 0;
    const int rowB  = tid >> 3;      // k row 0..31
    const int laneB = tid & 7;       // 16-half segment within 128-half row

    const int w    = tid >> 5;
    const int lane = tid & 31;
    const int mw   = (w & 1) * 64;
    const int nw   = (w >> 1) * 32;
    const int lr   = lane & 15;
    const int lc   = (lane >> 4) * 8;

    float acc[4][4][4];
    #pragma unroll
    for (int i = 0; i < 4; ++i)
        #pragma unroll
        for (int j = 0; j < 4; ++j)
            #pragma unroll
            for (int t = 0; t < 4; ++t) acc[i][j][t] = 0.f;

    const unsigned sbase = (unsigned)__cvta_generic_to_shared(smem_s);

    const __half* srcA_base = g_xh + (size_t)nodeA * 128 + segA * 16;
    const __half* srcB_base = g_wh + (size_t)(half * 128 + rowB) * 128 + laneB * 16;
    const unsigned dstA_off = (unsigned)(rA * ASK2 + segA * 16) * 2;
    const unsigned dstB_off = (unsigned)(ABUF + rowB * BSK + laneB * 16) * 2;

    auto load_chunk = [&](int c, int s) {
        unsigned sb = sbase + (unsigned)(s * STAGE_H) * 2;
        unsigned dA = sb + dstA_off;
        const __half* pA = srcA_base + c * 32;
        cp16(dA, pA);
        cp16(dA + 16, pA + 8);
        unsigned dB = sb + dstB_off;
        const __half* pB = srcB_base + (size_t)c * 32 * 128;
        cp16(dB, pB);
        cp16(dB + 16, pB + 8);
        cp_commit();
    };

    // two chunks in flight before the loop
    load_chunk(0, 0);
    load_chunk(1, 1);

    #pragma unroll
    for (int c = 0; c < 4; ++c) {
        const int s = c & 1;
        // chunk c resident; chunk c+1 may remain in flight
        if (c < 3) cp_wait<1>(); else cp_wait<0>();
        __syncthreads();                 // publish chunk c to all warps

        const unsigned sA0 = sbase + (unsigned)(s * STAGE_H) * 2;
        const unsigned sB0 = sA0 + (unsigned)ABUF * 2;

        #pragma unroll
        for (int ks = 0; ks < 2; ++ks) {
            const int k0 = ks * 16;
            unsigned a[4][4];
            #pragma unroll
            for (int mt = 0; mt < 4; ++mt) {
                unsigned addr = sA0 + ((mw + mt * 16 + lr) * ASK2 + k0 + lc) * 2;
                ldsm_x4(a[mt][0], a[mt][1], a[mt][2], a[mt][3], addr);
            }
            unsigned b[4][2];
            #pragma unroll
            for (int pr = 0; pr < 2; ++pr) {
                unsigned addr = sB0 + ((k0 + lr) * BSK + nw + pr * 16 + lc) * 2;
                unsigned r0, r1, r2, r3;
                ldsm_x4_t(r0, r1, r2, r3, addr);
                b[pr * 2][0] = r0;     b[pr * 2][1] = r1;
                b[pr * 2 + 1][0] = r2; b[pr * 2 + 1][1] = r3;
            }
            #pragma unroll
            for (int mt = 0; mt < 4; ++mt)
                #pragma unroll
                for (int nt = 0; nt < 4; ++nt)
                    mma16816(acc[mt][nt], a[mt], b[nt][0], b[nt][1]);
        }

        if (c < 2) {
            __syncthreads();             // all warps done reading stage s
            load_chunk(c + 2, s);        // refill it with chunk c+2
        }
    }
    __syncthreads();    // all mma reads done before epilogue staging overwrites buffers

    // ---- epilogue: +b1 (u half), fp16, stage through smem, coalesced copy ----
    const int g  = lane >> 2;
    const int t2 = (lane & 3) * 2;
    float bx[4], by[4];
    #pragma unroll
    for (int nt = 0; nt < 4; ++nt) {
        int c0 = nw + nt * 8 + t2;
        bx[nt] = (half == 0) ? b1[c0]     : 0.f;
        by[nt] = (half == 0) ? b1[c0 + 1] : 0.f;
    }

    __half* stage = smem_s;   // 128 x AST(136) halves = 34816 B, fits the pool
    #pragma unroll
    for (int mt = 0; mt < 4; ++mt) {
        #pragma unroll
        for (int nt = 0; nt < 4; ++nt) {
            int row = mw + mt * 16 + g;
            int col = nw + nt * 8 + t2;
            *(__half2*)(stage + row * AST + col) =
                __floats2half2_rn(acc[mt][nt][0] + bx[nt], acc[mt][nt][1] + by[nt]);
            *(__half2*)(stage + (row + 8) * AST + col) =
                __floats2half2_rn(acc[mt][nt][2] + bx[nt], acc[mt][nt][3] + by[nt]);
        }
    }
    __syncthreads();

    #pragma unroll
    for (int rr = 0; rr < 4; ++rr) {
        int r = w * 16 + rr * 4 + (lane >> 3);
        int node = base + r;
        if (node < n_nodes) {
            #pragma unroll
            for (int it = 0; it < 2; ++it) {
                int idx = (lane & 7) + it * 8;
                uint4 val = *(uint4*)(stage + r * AST + idx * 8);
                *(uint4*)(g_uv + (size_t)node * 256 + half * 128 + idx * 8) = val;
            }
        }
    }
}

// ---------------- edge phase v4: fp16 dot, u32 offsets (unchanged) ----------------
__global__ __launch_bounds__(256) void edge_eval(
    const void*  __restrict__ eidx,
    const float* __restrict__ b2,
    float* __restrict__ out,
    int E)
{
    const int lane = threadIdx.x & 31;
    const int hl   = lane & 15;       // feature group (8 features each)
    const int side = lane >> 4;       // which edge of each pair
    const int warp = blockIdx.x * 8 + (threadIdx.x >> 5);
    const long long e0 = (long long)warp * 8;
    if (e0 >= E) return;

    const uint4 w2p = ((const uint4*)g_w2h)[hl];     // 8 fp16 weights for this lane
    const __half2 w0 = bits_h2(w2p.x), w1 = bits_h2(w2p.y);
    const __half2 w2_ = bits_h2(w2p.z), w3 = bits_h2(w2p.w);
    const float  bias = b2[0];
    const int    is64 = g_idx_is64;
    const char* __restrict__ uvb = (const char*)g_uv;   // 512 B per node row

    int nr[4], nc[4];
    if (e0 + 8 <= E && (E & 1) == 0) {
        if (is64) {
            const longlong2* rp = (const longlong2*)eidx;
            #pragma unroll
            for (int t = 0; t < 4; ++t) {
                longlong2 rr = rp[(e0 >> 1) + t];
                nr[t] = (int)(side ? rr.y : rr.x);
                longlong2 cc = rp[(((long long)E + e0) >> 1) + t];
                nc[t] = (int)(side ? cc.y : cc.x);
            }
        } else {
            const int2* rp = (const int2*)eidx;
            #pragma unroll
            for (int t = 0; t < 4; ++t) {
                int2 rr = rp[(e0 >> 1) + t];
                nr[t] = side ? rr.y : rr.x;
                int2 cc = rp[(((long long)E + e0) >> 1) + t];
                nc[t] = side ? cc.y : cc.x;
            }
        }
    } else {
        #pragma unroll
        for (int t = 0; t < 4; ++t) {
            long long e = e0 + 2 * t + side;
            if (e >= E) e = e0;
            if (is64) {
                nr[t] = (int)((const long long*)eidx)[e];
                nc[t] = (int)((const long long*)eidx)[(long long)E + e];
            } else {
                nr[t] = ((const int*)eidx)[e];
                nc[t] = ((const int*)eidx)[(long long)E + e];
            }
        }
    }

    uint4 u[4], v[4];
    const unsigned hloff = (unsigned)hl * 16u;
    #pragma unroll
    for (int t = 0; t < 4; ++t) {
        u[t] = *(const uint4*)(uvb + ((unsigned)nr[t] * 512u + hloff));
        v[t] = *(const uint4*)(uvb + ((unsigned)nc[t] * 512u + 256u + hloff));
    }

    const __half2 z2 = __float2half2_rn(0.f);
    float s[4];
    #pragma unroll
    for (int t = 0; t < 4; ++t) {
        __half2 p0 = __hmax2(__hadd2(bits_h2(u[t].x), bits_h2(v[t].x)), z2);
        __half2 p1 = __hmax2(__hadd2(bits_h2(u[t].y), bits_h2(v[t].y)), z2);
        __half2 p2 = __hmax2(__hadd2(bits_h2(u[t].z), bits_h2(v[t].z)), z2);
        __half2 p3 = __hmax2(__hadd2(bits_h2(u[t].w), bits_h2(v[t].w)), z2);
        __half2 ah = __hmul2(p0, w0);
        ah = __hfma2(p1, w1, ah);
        ah = __hfma2(p2, w2_, ah);
        ah = __hfma2(p3, w3, ah);
        float2 f = __half22float2(ah);
        s[t] = f.x + f.y;
    }

    const unsigned FULLM = 0xffffffffu;
    const bool h8 = (hl & 8);
    float a0, a1;
    {
        float r0 = __shfl_xor_sync(FULLM, h8 ? s[0] : s[2], 8);
        a0 = (h8 ? s[2] : s[0]) + r0;
        float r1 = __shfl_xor_sync(FULLM, h8 ? s[1] : s[3], 8);
        a1 = (h8 ? s[3] : s[1]) + r1;
    }
    const bool h4 = (hl & 4);
    float b;
    {
        float r = __shfl_xor_sync(FULLM, h4 ? a0 : a1, 4);
        b = (h4 ? a1 : a0) + r;
    }
    b += __shfl_xor_sync(FULLM, b, 2);
    b += __shfl_xor_sync(FULLM, b, 1);

    int slot = ((hl >> 3) & 1) * 2 + ((hl >> 2) & 1);
    if ((hl & 3) == 0) {
        long long e = e0 + 2 * slot + side;
        if (e < E) out[e] = b + bias;
    }
}

extern "C" void kernel_launch(void* const* d_in, const int* in_sizes, int n_in,
                              void* d_out, int out_size)
{
    const float* x   = (const float*)d_in[0];
    const void*  ei  = d_in[1];
    const float* W1  = (const float*)d_in[2];
    const float* b1  = (const float*)d_in[3];
    const float* W2  = (const float*)d_in[4];
    const float* b2  = (const float*)d_in[5];
    float* out = (float*)d_out;

    int n_nodes = in_sizes[0] / 128;
    int E = in_sizes[1] / 2;

    long long total4 = (long long)n_nodes * 32;
    int cblocks = (int)((total4 / 2 + 255) / 256);
    convert_fp16<<<cblocks, 256>>>(x, W1, W2, ei, n_nodes);

    dim3 pgrid((n_nodes + 127) / 128, 2);
    precompute_uv<<<pgrid, NT>>>(b1, n_nodes);

    long long warps = ((long long)E + 7) / 8;
    int blocks = (int)((warps + 7) / 8);
    edge_eval<<<blocks, 256>>>(ei, b2, out, E);
}